// round 5
// baseline (speedup 1.0000x reference)
#include <cuda_runtime.h>
#include <math.h>

#define BATCH   16
#define T       640
#define EMBD    256
#define HEADS   8
#define DHDIM   32
#define BHDIM   128      // BATCH*HEADS
#define NHASH   8
#define NCHUNK  80
#define NROWS   10240    // BATCH*T

// ---------------- scratch (device globals; no allocation allowed) ----------------
__device__ float g_tokens[NROWS*EMBD];
__device__ float g_qk[BHDIM*T*DHDIM];
__device__ float g_v [BHDIM*T*DHDIM];
__device__ int   g_bucket[BHDIM*NHASH*T];
__device__ int   g_sorted[BHDIM*NHASH*T];
__device__ float g_ohash[(size_t)BHDIM*NHASH*T*DHDIM];
__device__ float g_logit[BHDIM*NHASH*T];
__device__ float g_omerged[NROWS*EMBD];

// ---------------- tf32 mma.sync helpers ----------------
__device__ __forceinline__ void mma_tf32(float* d, const unsigned* a, const unsigned* b){
  asm volatile(
    "mma.sync.aligned.m16n8k8.row.col.f32.tf32.tf32.f32 "
    "{%0,%1,%2,%3}, {%4,%5,%6,%7}, {%8,%9}, {%0,%1,%2,%3};"
    : "+f"(d[0]), "+f"(d[1]), "+f"(d[2]), "+f"(d[3])
    : "r"(a[0]), "r"(a[1]), "r"(a[2]), "r"(a[3]), "r"(b[0]), "r"(b[1]));
}
__device__ __forceinline__ unsigned tf32_rnd(float x){
  unsigned u; asm("cvt.rna.tf32.f32 %0, %1;" : "=r"(u) : "f"(x)); return u;
}
// split x into hi (tf32) + lo (tf32 of residual)
__device__ __forceinline__ void tf32_split(float x, unsigned &hi, unsigned &lo){
  hi = tf32_rnd(x);
  lo = tf32_rnd(x - __uint_as_float(hi));
}

// ---------------- stage 1: maxpool + Haar DWT -> tokens ----------------
__global__ void frontend_kernel(const float* __restrict__ x){
  int idx = blockIdx.x*blockDim.x + threadIdx.x;
  if (idx >= BATCH*640*256) return;
  int p = idx & 255;
  int n = (idx >> 8) % 640;
  int b = idx / (640*256);
  int i = p >> 4, j = p & 15;
  float val;
  if (n < 128){
    const float* xp = x + (size_t)(b*128+n)*1024;
    float m = -INFINITY;
    int r0 = 2*i-1, c0 = 2*j-1;
    #pragma unroll
    for (int dr=0;dr<3;dr++){
      int r = r0+dr; if (r<0 || r>31) continue;
      #pragma unroll
      for (int dc=0;dc<3;dc++){
        int cc = c0+dc; if (cc<0 || cc>31) continue;
        m = fmaxf(m, xp[r*32+cc]);
      }
    }
    val = m;
  } else {
    int g  = (n-128)>>7;
    int ch = (n-128)&127;
    const float* xp = x + (size_t)(b*128+ch)*1024;
    float a  = xp[(2*i)*32 + 2*j];
    float bb = xp[(2*i)*32 + 2*j+1];
    float c  = xp[(2*i+1)*32 + 2*j];
    float d  = xp[(2*i+1)*32 + 2*j+1];
    if      (g==0) val = (a+bb+c+d)*0.5f;
    else if (g==1) val = (a-bb+c-d)*0.5f;
    else if (g==2) val = (a+bb-c-d)*0.5f;
    else           val = (a-bb-c+d)*0.5f;
  }
  g_tokens[idx] = val;
}

// ---------------- stage 2: fused qk/v GEMM (fp32 exact), head-split epilogue ----------------
__global__ __launch_bounds__(256) void gemm_qkv_kernel(const float* __restrict__ Wqk,
                                                       const float* __restrict__ Wv){
  __shared__ float As [32][64];
  __shared__ float B1s[32][64];
  __shared__ float B2s[32][64];
  int tid = threadIdx.x;
  int m0 = blockIdx.y*64, n0 = blockIdx.x*64;
  int ty = tid>>4, tx = tid&15;
  float acc1[4][4], acc2[4][4];
  #pragma unroll
  for (int i=0;i<4;i++)
    #pragma unroll
    for (int j=0;j<4;j++){ acc1[i][j]=0.f; acc2[i][j]=0.f; }

  for (int k0=0;k0<256;k0+=32){
    int am = tid>>2, akq = tid&3;
    const float* asrc = g_tokens + (size_t)(m0+am)*256 + k0 + akq*8;
    float4 a0 = *(const float4*)asrc;
    float4 a1 = *(const float4*)(asrc+4);
    As[akq*8+0][am]=a0.x; As[akq*8+1][am]=a0.y; As[akq*8+2][am]=a0.z; As[akq*8+3][am]=a0.w;
    As[akq*8+4][am]=a1.x; As[akq*8+5][am]=a1.y; As[akq*8+6][am]=a1.z; As[akq*8+7][am]=a1.w;

    int bk = tid>>3, bnq = tid&7;
    const float* b1src = Wqk + (size_t)(k0+bk)*256 + n0 + bnq*8;
    const float* b2src = Wv  + (size_t)(k0+bk)*256 + n0 + bnq*8;
    *(float4*)&B1s[bk][bnq*8]   = *(const float4*)b1src;
    *(float4*)&B1s[bk][bnq*8+4] = *(const float4*)(b1src+4);
    *(float4*)&B2s[bk][bnq*8]   = *(const float4*)b2src;
    *(float4*)&B2s[bk][bnq*8+4] = *(const float4*)(b2src+4);
    __syncthreads();

    #pragma unroll
    for (int k=0;k<32;k++){
      float4 av = *(float4*)&As [k][ty*4];
      float4 b1 = *(float4*)&B1s[k][tx*4];
      float4 b2 = *(float4*)&B2s[k][tx*4];
      float aa[4]  = {av.x,av.y,av.z,av.w};
      float bb1[4] = {b1.x,b1.y,b1.z,b1.w};
      float bb2[4] = {b2.x,b2.y,b2.z,b2.w};
      #pragma unroll
      for (int i2=0;i2<4;i2++)
        #pragma unroll
        for (int j2=0;j2<4;j2++){
          acc1[i2][j2] += aa[i2]*bb1[j2];
          acc2[i2][j2] += aa[i2]*bb2[j2];
        }
    }
    __syncthreads();
  }
  #pragma unroll
  for (int i2=0;i2<4;i2++){
    int row = m0 + ty*4 + i2;
    int b = row/640, tok = row%640;
    #pragma unroll
    for (int j2=0;j2<4;j2++){
      int col = n0 + tx*4 + j2;
      int head = col>>5, dh = col&31;
      size_t o = ((size_t)(b*8+head)*640 + tok)*32 + dh;
      g_qk[o] = acc1[i2][j2];
      g_v [o] = acc2[i2][j2];
    }
  }
}

// ---------------- stage 3a: LSH bucket ids (fp32 exact) ----------------
__global__ void bucket_kernel(const float* __restrict__ rot){
  __shared__ float s_rot[32*NHASH*5];
  for (int i=threadIdx.x;i<1280;i+=blockDim.x) s_rot[i]=rot[i];
  __syncthreads();
  int idx = blockIdx.x*blockDim.x + threadIdx.x;
  if (idx >= BHDIM*NHASH*T) return;
  int pos = idx % 640;
  int h   = (idx/640) & 7;
  int bh  = idx / (NHASH*T);
  const float* q = g_qk + ((size_t)bh*640 + pos)*32;
  float r[5] = {0.f,0.f,0.f,0.f,0.f};
  #pragma unroll 8
  for (int f=0;f<32;f++){
    float qf = q[f];
    const float* rp = s_rot + f*40 + h*5;
    #pragma unroll
    for (int i=0;i<5;i++) r[i] += qf*rp[i];
  }
  float best = r[0]; int bi = 0;
  #pragma unroll
  for (int i=1;i<5;i++) if (r[i] > best){ best=r[i]; bi=i; }
  #pragma unroll
  for (int i=0;i<5;i++){ float v = -r[i]; if (v > best){ best=v; bi=5+i; } }
  g_bucket[idx] = bi;
}

// ---------------- stage 3b: stable counting sort per (bh, hash) ----------------
__global__ __launch_bounds__(320) void sort_kernel(){
  __shared__ int cnt[10], off[10];
  int bhh = blockIdx.x;
  const int* bk = g_bucket + bhh*640;
  int w = threadIdx.x>>5, lane = threadIdx.x&31;
  int count = 0;
  for (int base=0;base<640;base+=32){
    int bb = bk[base+lane];
    unsigned mask = __ballot_sync(0xffffffffu, bb==w);
    count += __popc(mask);
  }
  if (lane==0) cnt[w] = count;
  __syncthreads();
  if (threadIdx.x==0){
    int run=0;
    for (int b=0;b<10;b++){ off[b]=run; run+=cnt[b]; }
  }
  __syncthreads();
  int base_off = off[w]; int run = 0;
  int* out = g_sorted + bhh*640;
  for (int base=0;base<640;base+=32){
    int bb = bk[base+lane];
    unsigned mask = __ballot_sync(0xffffffffu, bb==w);
    if (bb==w){
      int slot = base_off + run + __popc(mask & ((1u<<lane)-1u));
      out[slot] = base+lane;
    }
    run += __popc(mask);
  }
}

// ---------------- stage 4: chunked attention, 3xTF32 mma.sync ----------------
#define Q_PAD 36
#define K_PAD 36
#define V_PAD 40
#define P_PAD 132
#define SMEM_ATTN ((64*P_PAD + 128*V_PAD + 2*128)*4 + (64+128)*4)

__global__ __launch_bounds__(256) void attn_kernel(){
  extern __shared__ char smem_raw[];
  float* s_p    = (float*)smem_raw;          // [64][132]
  float* s_q    = s_p;                       // [64][36]  alias
  float* s_k    = s_p + 64*Q_PAD;            // [128][36] alias
  float* s_v    = s_p + 64*P_PAD;            // [128][40]
  float* s_redm = s_v + 128*V_PAD;           // [2][64]
  float* s_reds = s_redm + 128;              // [2][64]
  int*   s_qt   = (int*)(s_reds + 128);      // [64]
  int*   s_kt   = s_qt + 64;                 // [128]

  int tid = threadIdx.x;
  int blk = blockIdx.x;
  int bh = blk / NCHUNK, c = blk % NCHUNK;
  int h  = c / 10;
  int pc = (c + NCHUNK - 1) % NCHUNK;
  int ph = pc / 10;
  const int* sortedbh = g_sorted + bh*NHASH*T;

  if (tid < 64)
    s_qt[tid] = sortedbh[h*640 + (c%10)*64 + tid];
  else if (tid < 192){
    int j = tid - 64;
    s_kt[j] = (j < 64) ? sortedbh[h*640 + (c%10)*64 + j]
                       : sortedbh[ph*640 + (pc%10)*64 + (j-64)];
  }
  __syncthreads();

  // Q row-major [64][36]
  {
    int i = tid >> 2, f0 = (tid & 3) * 8;
    const float* src = g_qk + ((size_t)bh*640 + s_qt[i])*32 + f0;
    *(float4*)&s_q[i*Q_PAD + f0]     = *(const float4*)src;
    *(float4*)&s_q[i*Q_PAD + f0 + 4] = *(const float4*)(src+4);
  }
  // K row-major [128][36], normalized
  {
    int j = tid >> 1, fh = (tid & 1) * 16;
    const float* src = g_qk + ((size_t)bh*640 + s_kt[j])*32 + fh;
    float buf[16]; float ss = 0.f;
    #pragma unroll
    for (int u=0;u<16;u+=4){
      float4 a = *(const float4*)(src+u);
      buf[u]=a.x; buf[u+1]=a.y; buf[u+2]=a.z; buf[u+3]=a.w;
      ss += a.x*a.x + a.y*a.y + a.z*a.z + a.w*a.w;
    }
    ss += __shfl_xor_sync(0xffffffffu, ss, 1);
    float inv = 1.f / fmaxf(sqrtf(ss), 1e-6f);
    #pragma unroll
    for (int u=0;u<16;u+=4)
      *(float4*)&s_k[j*K_PAD + fh + u] =
        make_float4(buf[u]*inv, buf[u+1]*inv, buf[u+2]*inv, buf[u+3]*inv);
  }
  // V row-major [128][40]
  {
    int j = tid >> 1, fh = (tid & 1) * 16;
    const float* src = g_v + ((size_t)bh*640 + s_kt[j])*32 + fh;
    #pragma unroll
    for (int u=0;u<16;u+=4)
      *(float4*)&s_v[j*V_PAD + fh + u] = *(const float4*)(src+u);
  }
  __syncthreads();

  // warp tiling: wm in 0..3 (16 query rows), wn in 0..1 (64-key half)
  int warp = tid >> 5, lane = tid & 31;
  int wm = warp & 3, wn = warp >> 2;
  int g = lane >> 2, tig = lane & 3;
  int m0 = wm * 16;
  int rA = m0 + g, rB = m0 + g + 8;

  // ---- dots: S(16x64 per warp) = Q x K^T, 3xTF32 ----
  float acc[8][4];
  #pragma unroll
  for (int nt=0;nt<8;nt++)
    #pragma unroll
    for (int u=0;u<4;u++) acc[nt][u] = 0.f;

  #pragma unroll
  for (int k0=0;k0<32;k0+=8){
    unsigned ah[4], al[4];
    tf32_split(s_q[rA*Q_PAD + k0 + tig],     ah[0], al[0]);
    tf32_split(s_q[rB*Q_PAD + k0 + tig],     ah[1], al[1]);
    tf32_split(s_q[rA*Q_PAD + k0 + tig + 4], ah[2], al[2]);
    tf32_split(s_q[rB*Q_PAD + k0 + tig + 4], ah[3], al[3]);
    #pragma unroll
    for (int nt=0;nt<8;nt++){
      int n0 = wn*64 + nt*8;
      unsigned bhh[2], bll[2];
      tf32_split(s_k[(n0+g)*K_PAD + k0 + tig],     bhh[0], bll[0]);
      tf32_split(s_k[(n0+g)*K_PAD + k0 + tig + 4], bhh[1], bll[1]);
      mma_tf32(acc[nt], ah, bhh);
      mma_tf32(acc[nt], al, bhh);
      mma_tf32(acc[nt], ah, bll);
    }
  }

  // scale + self-mask
  int qtA = s_qt[rA], qtB = s_qt[rB];
  #pragma unroll
  for (int nt=0;nt<8;nt++){
    int n0 = wn*64 + nt*8;
    int kt0 = s_kt[n0 + 2*tig], kt1 = s_kt[n0 + 2*tig + 1];
    acc[nt][0] = (kt0==qtA) ? -50000.f : acc[nt][0]*0.17677669529663687f;
    acc[nt][1] = (kt1==qtA) ? -50000.f : acc[nt][1]*0.17677669529663687f;
    acc[nt][2] = (kt0==qtB) ? -50000.f : acc[nt][2]*0.17677669529663687f;
    acc[nt][3] = (kt1==qtB) ? -50000.f : acc[nt][3]*0.17677669529663687f;
  }

  // partial row max over this warp's 64 cols
  float mA=-INFINITY, mB=-INFINITY;
  #pragma unroll
  for (int nt=0;nt<8;nt++){
    mA = fmaxf(mA, fmaxf(acc[nt][0], acc[nt][1]));
    mB = fmaxf(mB, fmaxf(acc[nt][2], acc[nt][3]));
  }
  #pragma unroll
  for (int o=1;o<=2;o<<=1){
    mA = fmaxf(mA, __shfl_xor_sync(0xffffffffu, mA, o, 4));
    mB = fmaxf(mB, __shfl_xor_sync(0xffffffffu, mB, o, 4));
  }
  // exp in place (reused later for probs), partial sums
  float sA=0.f, sB=0.f;
  #pragma unroll
  for (int nt=0;nt<8;nt++){
    acc[nt][0] = __expf(acc[nt][0]-mA);
    acc[nt][1] = __expf(acc[nt][1]-mA);
    acc[nt][2] = __expf(acc[nt][2]-mB);
    acc[nt][3] = __expf(acc[nt][3]-mB);
    sA += acc[nt][0] + acc[nt][1];
    sB += acc[nt][2] + acc[nt][3];
  }
  #pragma unroll
  for (int o=1;o<=2;o<<=1){
    sA += __shfl_xor_sync(0xffffffffu, sA, o, 4);
    sB += __shfl_xor_sync(0xffffffffu, sB, o, 4);
  }
  if (tig == 0){
    s_redm[wn*64 + rA] = mA;  s_reds[wn*64 + rA] = sA;
    s_redm[wn*64 + rB] = mB;  s_reds[wn*64 + rB] = sB;
  }
  __syncthreads();   // all dots-reads of s_q/s_k complete past this point

  float lseA, lseB;
  {
    float m0A = s_redm[rA], m1A = s_redm[64+rA];
    float mm = fmaxf(m0A, m1A);
    float ss = s_reds[rA]*__expf(m0A-mm) + s_reds[64+rA]*__expf(m1A-mm);
    lseA = mm + __logf(ss);
    float m0B = s_redm[rB], m1B = s_redm[64+rB];
    mm = fmaxf(m0B, m1B);
    ss = s_reds[rB]*__expf(m0B-mm) + s_reds[64+rB]*__expf(m1B-mm);
    lseB = mm + __logf(ss);
  }
  if (wn == 0 && tig == 0){
    g_logit[(bh*NHASH+h)*T + qtA] = lseA;
    g_logit[(bh*NHASH+h)*T + qtB] = lseB;
  }

  // probs into s_p: reuse stored exp(acc-m), rescale by exp(m - lse)
  float scA = __expf(mA - lseA);
  float scB = __expf(mB - lseB);
  #pragma unroll
  for (int nt=0;nt<8;nt++){
    int n0 = wn*64 + nt*8;
    *(float2*)&s_p[rA*P_PAD + n0 + 2*tig] =
      make_float2(acc[nt][0]*scA, acc[nt][1]*scA);
    *(float2*)&s_p[rB*P_PAD + n0 + 2*tig] =
      make_float2(acc[nt][2]*scB, acc[nt][3]*scB);
  }
  __syncthreads();

  // ---- PV: O(16x16 per warp) = P(16x128) x V(128x32), 3xTF32 ----
  float o0[4] = {0.f,0.f,0.f,0.f};
  float o1[4] = {0.f,0.f,0.f,0.f};
  int d0 = wn*16;
  #pragma unroll 2
  for (int k0=0;k0<128;k0+=8){
    unsigned ah[4], al[4];
    tf32_split(s_p[rA*P_PAD + k0 + tig],     ah[0], al[0]);
    tf32_split(s_p[rB*P_PAD + k0 + tig],     ah[1], al[1]);
    tf32_split(s_p[rA*P_PAD + k0 + tig + 4], ah[2], al[2]);
    tf32_split(s_p[rB*P_PAD + k0 + tig + 4], ah[3], al[3]);
    unsigned b0h[2], b0l[2], b1h[2], b1l[2];
    tf32_split(s_v[(k0+tig)*V_PAD   + d0 + g],     b0h[0], b0l[0]);
    tf32_split(s_v[(k0+tig+4)*V_PAD + d0 + g],     b0h[1], b0l[1]);
    tf32_split(s_v[(k0+tig)*V_PAD   + d0 + 8 + g], b1h[0], b1l[0]);
    tf32_split(s_v[(k0+tig+4)*V_PAD + d0 + 8 + g], b1h[1], b1l[1]);
    mma_tf32(o0, ah, b0h);
    mma_tf32(o0, al, b0h);
    mma_tf32(o0, ah, b0l);
    mma_tf32(o1, ah, b1h);
    mma_tf32(o1, al, b1h);
    mma_tf32(o1, ah, b1l);
  }
  {
    size_t base = (size_t)(bh*NHASH+h)*T;
    float* dA = g_ohash + (base + qtA)*32;
    float* dB = g_ohash + (base + qtB)*32;
    *(float2*)(dA + d0 + 2*tig)     = make_float2(o0[0], o0[1]);
    *(float2*)(dB + d0 + 2*tig)     = make_float2(o0[2], o0[3]);
    *(float2*)(dA + d0 + 8 + 2*tig) = make_float2(o1[0], o1[1]);
    *(float2*)(dB + d0 + 8 + 2*tig) = make_float2(o1[2], o1[3]);
  }
}

// ---------------- stage 5: combine hashes, merge heads (float4) ----------------
__global__ void combine_kernel(){
  int idx = blockIdx.x*blockDim.x + threadIdx.x;
  if (idx >= BHDIM*T*8) return;
  int dq  = idx & 7;
  int pos = (idx >> 3) % 640;
  int bh  = idx / (640*8);
  float l[NHASH];
  #pragma unroll
  for (int h=0;h<NHASH;h++) l[h] = g_logit[(bh*NHASH+h)*T + pos];
  float m = l[0];
  #pragma unroll
  for (int h=1;h<NHASH;h++) m = fmaxf(m, l[h]);
  float s = 0.f;
  float e[NHASH];
  #pragma unroll
  for (int h=0;h<NHASH;h++){ e[h] = __expf(l[h]-m); s += e[h]; }
  float inv = 1.f/s;
  float4 acc = make_float4(0.f,0.f,0.f,0.f);
  #pragma unroll
  for (int h=0;h<NHASH;h++){
    float w = e[h]*inv;
    float4 v = *(const float4*)(g_ohash + ((size_t)(bh*NHASH+h)*T + pos)*32 + dq*4);
    acc.x += w*v.x; acc.y += w*v.y; acc.z += w*v.z; acc.w += w*v.w;
  }
  int b = bh>>3, head = bh&7;
  *(float4*)(g_omerged + ((size_t)b*640 + pos)*256 + head*32 + dq*4) = acc;
}

// ---------------- stage 6: output GEMM + bias (fp32) ----------------
__global__ __launch_bounds__(256) void gemm_out_kernel(const float* __restrict__ W,
                                                       const float* __restrict__ bias,
                                                       float* __restrict__ out){
  __shared__ float As[32][64];
  __shared__ float Bs[32][64];
  int tid = threadIdx.x;
  int m0 = blockIdx.y*64, n0 = blockIdx.x*64;
  int ty = tid>>4, tx = tid&15;
  float acc[4][4];
  #pragma unroll
  for (int i=0;i<4;i++)
    #pragma unroll
    for (int j=0;j<4;j++) acc[i][j]=0.f;

  for (int k0=0;k0<256;k0+=32){
    int am = tid>>2, akq = tid&3;
    const float* asrc = g_omerged + (size_t)(m0+am)*256 + k0 + akq*8;
    float4 a0 = *(const float4*)asrc;
    float4 a1 = *(const float4*)(asrc+4);
    As[akq*8+0][am]=a0.x; As[akq*8+1][am]=a0.y; As[akq*8+2][am]=a0.z; As[akq*8+3][am]=a0.w;
    As[akq*8+4][am]=a1.x; As[akq*8+5][am]=a1.y; As[akq*8+6][am]=a1.z; As[akq*8+7][am]=a1.w;

    int bk = tid>>3, bnq = tid&7;
    const float* bsrc = W + (size_t)(k0+bk)*256 + n0 + bnq*8;
    *(float4*)&Bs[bk][bnq*8]   = *(const float4*)bsrc;
    *(float4*)&Bs[bk][bnq*8+4] = *(const float4*)(bsrc+4);
    __syncthreads();

    #pragma unroll
    for (int k=0;k<32;k++){
      float4 av = *(float4*)&As[k][ty*4];
      float4 bv = *(float4*)&Bs[k][tx*4];
      float aa[4] = {av.x,av.y,av.z,av.w};
      float bb[4] = {bv.x,bv.y,bv.z,bv.w};
      #pragma unroll
      for (int i2=0;i2<4;i2++)
        #pragma unroll
        for (int j2=0;j2<4;j2++) acc[i2][j2] += aa[i2]*bb[j2];
    }
    __syncthreads();
  }
  #pragma unroll
  for (int i2=0;i2<4;i2++){
    int row = m0 + ty*4 + i2;
    #pragma unroll
    for (int j2=0;j2<4;j2++){
      int col = n0 + tx*4 + j2;
      out[(size_t)row*256 + col] = acc[i2][j2] + bias[col];
    }
  }
}

// ---------------- launch ----------------
extern "C" void kernel_launch(void* const* d_in, const int* in_sizes, int n_in,
                              void* d_out, int out_size){
  const float* x     = (const float*)d_in[0];
  const float* w_qk  = (const float*)d_in[1];
  const float* w_v   = (const float*)d_in[2];
  const float* w_out = (const float*)d_in[3];
  const float* b_out = (const float*)d_in[4];
  const float* rot   = (const float*)d_in[5];
  float* out = (float*)d_out;

  frontend_kernel<<<(BATCH*640*256+255)/256, 256>>>(x);
  gemm_qkv_kernel<<<dim3(4,160), 256>>>(w_qk, w_v);
  bucket_kernel<<<(BHDIM*NHASH*T+255)/256, 256>>>(rot);
  sort_kernel<<<BHDIM*NHASH, 320>>>();
  cudaFuncSetAttribute(attn_kernel, cudaFuncAttributeMaxDynamicSharedMemorySize, SMEM_ATTN);
  attn_kernel<<<BHDIM*NCHUNK, 256, SMEM_ATTN>>>();
  combine_kernel<<<(BHDIM*T*8+255)/256, 256>>>();
  gemm_out_kernel<<<dim3(4,160), 256>>>(w_out, b_out, out);
}

// round 6
// speedup vs baseline: 1.1502x; 1.1502x over previous
#include <cuda_runtime.h>
#include <math.h>

#define BATCH   16
#define T       640
#define EMBD    256
#define HEADS   8
#define DHDIM   32
#define BHDIM   128      // BATCH*HEADS
#define NHASH   8
#define NCHUNK  80
#define NROWS   10240    // BATCH*T

// ---------------- scratch (device globals; no allocation allowed) ----------------
__device__ float g_tokens[NROWS*EMBD];
__device__ float g_qk[BHDIM*T*DHDIM];
__device__ float g_v [BHDIM*T*DHDIM];
__device__ int   g_bucket[BHDIM*NHASH*T];
__device__ int   g_sorted[BHDIM*NHASH*T];
__device__ float g_ohash[(size_t)BHDIM*NHASH*T*DHDIM];
__device__ float g_logit[BHDIM*NHASH*T];
__device__ float g_omerged[NROWS*EMBD];

// ---------------- tf32 mma.sync helpers ----------------
__device__ __forceinline__ void mma_tf32(float* d, const unsigned* a, const unsigned* b){
  asm volatile(
    "mma.sync.aligned.m16n8k8.row.col.f32.tf32.tf32.f32 "
    "{%0,%1,%2,%3}, {%4,%5,%6,%7}, {%8,%9}, {%0,%1,%2,%3};"
    : "+f"(d[0]), "+f"(d[1]), "+f"(d[2]), "+f"(d[3])
    : "r"(a[0]), "r"(a[1]), "r"(a[2]), "r"(a[3]), "r"(b[0]), "r"(b[1]));
}
// cheap split: hi = x with low 13 mantissa bits zeroed (exact tf32 value),
// lo = x - hi. One LOP + one FADD instead of two 20-cyc cvt.rna.
__device__ __forceinline__ void tf32_split(float x, unsigned &hi, unsigned &lo){
  unsigned hb = __float_as_uint(x) & 0xFFFFE000u;
  hi = hb;
  lo = __float_as_uint(x - __uint_as_float(hb));
}

// ---------------- stage 1: maxpool + Haar DWT -> tokens ----------------
__global__ void frontend_kernel(const float* __restrict__ x){
  int idx = blockIdx.x*blockDim.x + threadIdx.x;
  if (idx >= BATCH*640*256) return;
  int p = idx & 255;
  int n = (idx >> 8) % 640;
  int b = idx / (640*256);
  int i = p >> 4, j = p & 15;
  float val;
  if (n < 128){
    const float* xp = x + (size_t)(b*128+n)*1024;
    float m = -INFINITY;
    int r0 = 2*i-1, c0 = 2*j-1;
    #pragma unroll
    for (int dr=0;dr<3;dr++){
      int r = r0+dr; if (r<0 || r>31) continue;
      #pragma unroll
      for (int dc=0;dc<3;dc++){
        int cc = c0+dc; if (cc<0 || cc>31) continue;
        m = fmaxf(m, xp[r*32+cc]);
      }
    }
    val = m;
  } else {
    int g  = (n-128)>>7;
    int ch = (n-128)&127;
    const float* xp = x + (size_t)(b*128+ch)*1024;
    float a  = xp[(2*i)*32 + 2*j];
    float bb = xp[(2*i)*32 + 2*j+1];
    float c  = xp[(2*i+1)*32 + 2*j];
    float d  = xp[(2*i+1)*32 + 2*j+1];
    if      (g==0) val = (a+bb+c+d)*0.5f;
    else if (g==1) val = (a-bb+c-d)*0.5f;
    else if (g==2) val = (a+bb-c-d)*0.5f;
    else           val = (a-bb-c+d)*0.5f;
  }
  g_tokens[idx] = val;
}

// ---------------- stage 2: fused qk/v GEMM (fp32 exact), 128x64 tiles ----------------
__global__ __launch_bounds__(256) void gemm_qkv_kernel(const float* __restrict__ Wqk,
                                                       const float* __restrict__ Wv){
  __shared__ float As [32][128];
  __shared__ float B1s[32][64];
  __shared__ float B2s[32][64];
  int tid = threadIdx.x;
  int m0 = blockIdx.y*128, n0 = blockIdx.x*64;
  int ty = tid>>4, tx = tid&15;     // rows ty*8..+7, cols tx*4..+3
  float acc1[8][4], acc2[8][4];
  #pragma unroll
  for (int i=0;i<8;i++)
    #pragma unroll
    for (int j=0;j<4;j++){ acc1[i][j]=0.f; acc2[i][j]=0.f; }

  for (int k0=0;k0<256;k0+=32){
    // A: 128 rows x 32 k, transposed store
    {
      int am = tid>>1, ak = (tid&1)*16;
      const float* asrc = g_tokens + (size_t)(m0+am)*256 + k0 + ak;
      float4 a0 = *(const float4*)asrc;
      float4 a1 = *(const float4*)(asrc+4);
      float4 a2 = *(const float4*)(asrc+8);
      float4 a3 = *(const float4*)(asrc+12);
      As[ak+ 0][am]=a0.x; As[ak+ 1][am]=a0.y; As[ak+ 2][am]=a0.z; As[ak+ 3][am]=a0.w;
      As[ak+ 4][am]=a1.x; As[ak+ 5][am]=a1.y; As[ak+ 6][am]=a1.z; As[ak+ 7][am]=a1.w;
      As[ak+ 8][am]=a2.x; As[ak+ 9][am]=a2.y; As[ak+10][am]=a2.z; As[ak+11][am]=a2.w;
      As[ak+12][am]=a3.x; As[ak+13][am]=a3.y; As[ak+14][am]=a3.z; As[ak+15][am]=a3.w;
    }
    // B: 32 k x 64 n, each thread 2 float4 per matrix
    {
      int bk = tid>>3, bn = (tid&7)*8;
      const float* b1src = Wqk + (size_t)(k0+bk)*256 + n0 + bn;
      const float* b2src = Wv  + (size_t)(k0+bk)*256 + n0 + bn;
      *(float4*)&B1s[bk][bn]   = *(const float4*)b1src;
      *(float4*)&B1s[bk][bn+4] = *(const float4*)(b1src+4);
      *(float4*)&B2s[bk][bn]   = *(const float4*)b2src;
      *(float4*)&B2s[bk][bn+4] = *(const float4*)(b2src+4);
    }
    __syncthreads();

    #pragma unroll
    for (int k=0;k<32;k++){
      float4 a0 = *(float4*)&As[k][ty*8];
      float4 a1 = *(float4*)&As[k][ty*8+4];
      float4 b1 = *(float4*)&B1s[k][tx*4];
      float4 b2 = *(float4*)&B2s[k][tx*4];
      float aa[8]  = {a0.x,a0.y,a0.z,a0.w,a1.x,a1.y,a1.z,a1.w};
      float bb1[4] = {b1.x,b1.y,b1.z,b1.w};
      float bb2[4] = {b2.x,b2.y,b2.z,b2.w};
      #pragma unroll
      for (int i2=0;i2<8;i2++)
        #pragma unroll
        for (int j2=0;j2<4;j2++){
          acc1[i2][j2] += aa[i2]*bb1[j2];
          acc2[i2][j2] += aa[i2]*bb2[j2];
        }
    }
    __syncthreads();
  }
  // epilogue: head-split layout; 4 consecutive cols stay within one head
  int col = n0 + tx*4;
  int head = col>>5, dh = col&31;
  #pragma unroll
  for (int i2=0;i2<8;i2++){
    int row = m0 + ty*8 + i2;
    int b = row/640, tok = row%640;
    size_t o = ((size_t)(b*8+head)*640 + tok)*32 + dh;
    *(float4*)&g_qk[o] = make_float4(acc1[i2][0],acc1[i2][1],acc1[i2][2],acc1[i2][3]);
    *(float4*)&g_v [o] = make_float4(acc2[i2][0],acc2[i2][1],acc2[i2][2],acc2[i2][3]);
  }
}

// ---------------- stage 3a: LSH bucket ids (fp32 exact) ----------------
__global__ void bucket_kernel(const float* __restrict__ rot){
  __shared__ float s_rot[32*NHASH*5];
  for (int i=threadIdx.x;i<1280;i+=blockDim.x) s_rot[i]=rot[i];
  __syncthreads();
  int idx = blockIdx.x*blockDim.x + threadIdx.x;
  if (idx >= BHDIM*NHASH*T) return;
  int pos = idx % 640;
  int h   = (idx/640) & 7;
  int bh  = idx / (NHASH*T);
  const float* q = g_qk + ((size_t)bh*640 + pos)*32;
  float r[5] = {0.f,0.f,0.f,0.f,0.f};
  #pragma unroll 8
  for (int f=0;f<32;f++){
    float qf = q[f];
    const float* rp = s_rot + f*40 + h*5;
    #pragma unroll
    for (int i=0;i<5;i++) r[i] += qf*rp[i];
  }
  float best = r[0]; int bi = 0;
  #pragma unroll
  for (int i=1;i<5;i++) if (r[i] > best){ best=r[i]; bi=i; }
  #pragma unroll
  for (int i=0;i<5;i++){ float v = -r[i]; if (v > best){ best=v; bi=5+i; } }
  g_bucket[idx] = bi;
}

// ---------------- stage 3b: stable counting sort per (bh, hash) ----------------
__global__ __launch_bounds__(320) void sort_kernel(){
  __shared__ int cnt[10], off[10];
  int bhh = blockIdx.x;
  const int* bk = g_bucket + bhh*640;
  int w = threadIdx.x>>5, lane = threadIdx.x&31;
  int count = 0;
  for (int base=0;base<640;base+=32){
    int bb = bk[base+lane];
    unsigned mask = __ballot_sync(0xffffffffu, bb==w);
    count += __popc(mask);
  }
  if (lane==0) cnt[w] = count;
  __syncthreads();
  if (threadIdx.x==0){
    int run=0;
    for (int b=0;b<10;b++){ off[b]=run; run+=cnt[b]; }
  }
  __syncthreads();
  int base_off = off[w]; int run = 0;
  int* out = g_sorted + bhh*640;
  for (int base=0;base<640;base+=32){
    int bb = bk[base+lane];
    unsigned mask = __ballot_sync(0xffffffffu, bb==w);
    if (bb==w){
      int slot = base_off + run + __popc(mask & ((1u<<lane)-1u));
      out[slot] = base+lane;
    }
    run += __popc(mask);
  }
}

// ---------------- stage 4: chunked attention, 3xTF32 mma.sync (mask splits) ----------------
#define Q_PAD 36
#define K_PAD 36
#define V_PAD 40
#define P_PAD 132
#define SMEM_ATTN ((64*P_PAD + 128*V_PAD + 2*128)*4 + (64+128)*4)

__global__ __launch_bounds__(256) void attn_kernel(){
  extern __shared__ char smem_raw[];
  float* s_p    = (float*)smem_raw;          // [64][132]
  float* s_q    = s_p;                       // [64][36]  alias
  float* s_k    = s_p + 64*Q_PAD;            // [128][36] alias
  float* s_v    = s_p + 64*P_PAD;            // [128][40]
  float* s_redm = s_v + 128*V_PAD;           // [2][64]
  float* s_reds = s_redm + 128;              // [2][64]
  int*   s_qt   = (int*)(s_reds + 128);      // [64]
  int*   s_kt   = s_qt + 64;                 // [128]

  int tid = threadIdx.x;
  int blk = blockIdx.x;
  int bh = blk / NCHUNK, c = blk % NCHUNK;
  int h  = c / 10;
  int pc = (c + NCHUNK - 1) % NCHUNK;
  int ph = pc / 10;
  const int* sortedbh = g_sorted + bh*NHASH*T;

  if (tid < 64)
    s_qt[tid] = sortedbh[h*640 + (c%10)*64 + tid];
  else if (tid < 192){
    int j = tid - 64;
    s_kt[j] = (j < 64) ? sortedbh[h*640 + (c%10)*64 + j]
                       : sortedbh[ph*640 + (pc%10)*64 + (j-64)];
  }
  __syncthreads();

  // Q row-major [64][36]
  {
    int i = tid >> 2, f0 = (tid & 3) * 8;
    const float* src = g_qk + ((size_t)bh*640 + s_qt[i])*32 + f0;
    *(float4*)&s_q[i*Q_PAD + f0]     = *(const float4*)src;
    *(float4*)&s_q[i*Q_PAD + f0 + 4] = *(const float4*)(src+4);
  }
  // K row-major [128][36], normalized
  {
    int j = tid >> 1, fh = (tid & 1) * 16;
    const float* src = g_qk + ((size_t)bh*640 + s_kt[j])*32 + fh;
    float buf[16]; float ss = 0.f;
    #pragma unroll
    for (int u=0;u<16;u+=4){
      float4 a = *(const float4*)(src+u);
      buf[u]=a.x; buf[u+1]=a.y; buf[u+2]=a.z; buf[u+3]=a.w;
      ss += a.x*a.x + a.y*a.y + a.z*a.z + a.w*a.w;
    }
    ss += __shfl_xor_sync(0xffffffffu, ss, 1);
    float inv = 1.f / fmaxf(sqrtf(ss), 1e-6f);
    #pragma unroll
    for (int u=0;u<16;u+=4)
      *(float4*)&s_k[j*K_PAD + fh + u] =
        make_float4(buf[u]*inv, buf[u+1]*inv, buf[u+2]*inv, buf[u+3]*inv);
  }
  // V row-major [128][40]
  {
    int j = tid >> 1, fh = (tid & 1) * 16;
    const float* src = g_v + ((size_t)bh*640 + s_kt[j])*32 + fh;
    #pragma unroll
    for (int u=0;u<16;u+=4)
      *(float4*)&s_v[j*V_PAD + fh + u] = *(const float4*)(src+u);
  }
  __syncthreads();

  // warp tiling: wm in 0..3 (16 query rows), wn in 0..1 (64-key half)
  int warp = tid >> 5, lane = tid & 31;
  int wm = warp & 3, wn = warp >> 2;
  int g = lane >> 2, tig = lane & 3;
  int m0 = wm * 16;
  int rA = m0 + g, rB = m0 + g + 8;

  // ---- dots: S(16x64 per warp) = Q x K^T, 3xTF32 ----
  float acc[8][4];
  #pragma unroll
  for (int nt=0;nt<8;nt++)
    #pragma unroll
    for (int u=0;u<4;u++) acc[nt][u] = 0.f;

  #pragma unroll
  for (int k0=0;k0<32;k0+=8){
    unsigned ah[4], al[4];
    tf32_split(s_q[rA*Q_PAD + k0 + tig],     ah[0], al[0]);
    tf32_split(s_q[rB*Q_PAD + k0 + tig],     ah[1], al[1]);
    tf32_split(s_q[rA*Q_PAD + k0 + tig + 4], ah[2], al[2]);
    tf32_split(s_q[rB*Q_PAD + k0 + tig + 4], ah[3], al[3]);
    #pragma unroll
    for (int nt=0;nt<8;nt++){
      int n0 = wn*64 + nt*8;
      unsigned bhh[2], bll[2];
      tf32_split(s_k[(n0+g)*K_PAD + k0 + tig],     bhh[0], bll[0]);
      tf32_split(s_k[(n0+g)*K_PAD + k0 + tig + 4], bhh[1], bll[1]);
      mma_tf32(acc[nt], ah, bhh);
      mma_tf32(acc[nt], al, bhh);
      mma_tf32(acc[nt], ah, bll);
    }
  }

  // scale + self-mask
  int qtA = s_qt[rA], qtB = s_qt[rB];
  #pragma unroll
  for (int nt=0;nt<8;nt++){
    int n0 = wn*64 + nt*8;
    int kt0 = s_kt[n0 + 2*tig], kt1 = s_kt[n0 + 2*tig + 1];
    acc[nt][0] = (kt0==qtA) ? -50000.f : acc[nt][0]*0.17677669529663687f;
    acc[nt][1] = (kt1==qtA) ? -50000.f : acc[nt][1]*0.17677669529663687f;
    acc[nt][2] = (kt0==qtB) ? -50000.f : acc[nt][2]*0.17677669529663687f;
    acc[nt][3] = (kt1==qtB) ? -50000.f : acc[nt][3]*0.17677669529663687f;
  }

  // partial row max over this warp's 64 cols
  float mA=-INFINITY, mB=-INFINITY;
  #pragma unroll
  for (int nt=0;nt<8;nt++){
    mA = fmaxf(mA, fmaxf(acc[nt][0], acc[nt][1]));
    mB = fmaxf(mB, fmaxf(acc[nt][2], acc[nt][3]));
  }
  #pragma unroll
  for (int o=1;o<=2;o<<=1){
    mA = fmaxf(mA, __shfl_xor_sync(0xffffffffu, mA, o, 4));
    mB = fmaxf(mB, __shfl_xor_sync(0xffffffffu, mB, o, 4));
  }
  // exp in place (reused later for probs), partial sums
  float sA=0.f, sB=0.f;
  #pragma unroll
  for (int nt=0;nt<8;nt++){
    acc[nt][0] = __expf(acc[nt][0]-mA);
    acc[nt][1] = __expf(acc[nt][1]-mA);
    acc[nt][2] = __expf(acc[nt][2]-mB);
    acc[nt][3] = __expf(acc[nt][3]-mB);
    sA += acc[nt][0] + acc[nt][1];
    sB += acc[nt][2] + acc[nt][3];
  }
  #pragma unroll
  for (int o=1;o<=2;o<<=1){
    sA += __shfl_xor_sync(0xffffffffu, sA, o, 4);
    sB += __shfl_xor_sync(0xffffffffu, sB, o, 4);
  }
  if (tig == 0){
    s_redm[wn*64 + rA] = mA;  s_reds[wn*64 + rA] = sA;
    s_redm[wn*64 + rB] = mB;  s_reds[wn*64 + rB] = sB;
  }
  __syncthreads();   // all dots-reads of s_q/s_k complete past this point

  float lseA, lseB;
  {
    float m0A = s_redm[rA], m1A = s_redm[64+rA];
    float mm = fmaxf(m0A, m1A);
    float ss = s_reds[rA]*__expf(m0A-mm) + s_reds[64+rA]*__expf(m1A-mm);
    lseA = mm + __logf(ss);
    float m0B = s_redm[rB], m1B = s_redm[64+rB];
    mm = fmaxf(m0B, m1B);
    ss = s_reds[rB]*__expf(m0B-mm) + s_reds[64+rB]*__expf(m1B-mm);
    lseB = mm + __logf(ss);
  }
  if (wn == 0 && tig == 0){
    g_logit[(bh*NHASH+h)*T + qtA] = lseA;
    g_logit[(bh*NHASH+h)*T + qtB] = lseB;
  }

  // probs into s_p: reuse stored exp(acc-m), rescale by exp(m - lse)
  float scA = __expf(mA - lseA);
  float scB = __expf(mB - lseB);
  #pragma unroll
  for (int nt=0;nt<8;nt++){
    int n0 = wn*64 + nt*8;
    *(float2*)&s_p[rA*P_PAD + n0 + 2*tig] =
      make_float2(acc[nt][0]*scA, acc[nt][1]*scA);
    *(float2*)&s_p[rB*P_PAD + n0 + 2*tig] =
      make_float2(acc[nt][2]*scB, acc[nt][3]*scB);
  }
  __syncthreads();

  // ---- PV: O(16x16 per warp) = P(16x128) x V(128x32), 3xTF32 ----
  float o0[4] = {0.f,0.f,0.f,0.f};
  float o1[4] = {0.f,0.f,0.f,0.f};
  int d0 = wn*16;
  #pragma unroll 2
  for (int k0=0;k0<128;k0+=8){
    unsigned ah[4], al[4];
    tf32_split(s_p[rA*P_PAD + k0 + tig],     ah[0], al[0]);
    tf32_split(s_p[rB*P_PAD + k0 + tig],     ah[1], al[1]);
    tf32_split(s_p[rA*P_PAD + k0 + tig + 4], ah[2], al[2]);
    tf32_split(s_p[rB*P_PAD + k0 + tig + 4], ah[3], al[3]);
    unsigned b0h[2], b0l[2], b1h[2], b1l[2];
    tf32_split(s_v[(k0+tig)*V_PAD   + d0 + g],     b0h[0], b0l[0]);
    tf32_split(s_v[(k0+tig+4)*V_PAD + d0 + g],     b0h[1], b0l[1]);
    tf32_split(s_v[(k0+tig)*V_PAD   + d0 + 8 + g], b1h[0], b1l[0]);
    tf32_split(s_v[(k0+tig+4)*V_PAD + d0 + 8 + g], b1h[1], b1l[1]);
    mma_tf32(o0, ah, b0h);
    mma_tf32(o0, al, b0h);
    mma_tf32(o0, ah, b0l);
    mma_tf32(o1, ah, b1h);
    mma_tf32(o1, al, b1h);
    mma_tf32(o1, ah, b1l);
  }
  {
    size_t base = (size_t)(bh*NHASH+h)*T;
    float* dA = g_ohash + (base + qtA)*32;
    float* dB = g_ohash + (base + qtB)*32;
    *(float2*)(dA + d0 + 2*tig)     = make_float2(o0[0], o0[1]);
    *(float2*)(dB + d0 + 2*tig)     = make_float2(o0[2], o0[3]);
    *(float2*)(dA + d0 + 8 + 2*tig) = make_float2(o1[0], o1[1]);
    *(float2*)(dB + d0 + 8 + 2*tig) = make_float2(o1[2], o1[3]);
  }
}

// ---------------- stage 5: combine hashes, merge heads (float4) ----------------
__global__ void combine_kernel(){
  int idx = blockIdx.x*blockDim.x + threadIdx.x;
  if (idx >= BHDIM*T*8) return;
  int dq  = idx & 7;
  int pos = (idx >> 3) % 640;
  int bh  = idx / (640*8);
  float l[NHASH];
  #pragma unroll
  for (int h=0;h<NHASH;h++) l[h] = g_logit[(bh*NHASH+h)*T + pos];
  float m = l[0];
  #pragma unroll
  for (int h=1;h<NHASH;h++) m = fmaxf(m, l[h]);
  float s = 0.f;
  float e[NHASH];
  #pragma unroll
  for (int h=0;h<NHASH;h++){ e[h] = __expf(l[h]-m); s += e[h]; }
  float inv = 1.f/s;
  float4 acc = make_float4(0.f,0.f,0.f,0.f);
  #pragma unroll
  for (int h=0;h<NHASH;h++){
    float w = e[h]*inv;
    float4 v = *(const float4*)(g_ohash + ((size_t)(bh*NHASH+h)*T + pos)*32 + dq*4);
    acc.x += w*v.x; acc.y += w*v.y; acc.z += w*v.z; acc.w += w*v.w;
  }
  int b = bh>>3, head = bh&7;
  *(float4*)(g_omerged + ((size_t)b*640 + pos)*256 + head*32 + dq*4) = acc;
}

// ---------------- stage 6: output GEMM + bias (fp32), 128x64 tiles ----------------
__global__ __launch_bounds__(256) void gemm_out_kernel(const float* __restrict__ W,
                                                       const float* __restrict__ bias,
                                                       float* __restrict__ out){
  __shared__ float As[32][128];
  __shared__ float Bs[32][64];
  int tid = threadIdx.x;
  int m0 = blockIdx.y*128, n0 = blockIdx.x*64;
  int ty = tid>>4, tx = tid&15;
  float acc[8][4];
  #pragma unroll
  for (int i=0;i<8;i++)
    #pragma unroll
    for (int j=0;j<4;j++) acc[i][j]=0.f;

  for (int k0=0;k0<256;k0+=32){
    {
      int am = tid>>1, ak = (tid&1)*16;
      const float* asrc = g_omerged + (size_t)(m0+am)*256 + k0 + ak;
      float4 a0 = *(const float4*)asrc;
      float4 a1 = *(const float4*)(asrc+4);
      float4 a2 = *(const float4*)(asrc+8);
      float4 a3 = *(const float4*)(asrc+12);
      As[ak+ 0][am]=a0.x; As[ak+ 1][am]=a0.y; As[ak+ 2][am]=a0.z; As[ak+ 3][am]=a0.w;
      As[ak+ 4][am]=a1.x; As[ak+ 5][am]=a1.y; As[ak+ 6][am]=a1.z; As[ak+ 7][am]=a1.w;
      As[ak+ 8][am]=a2.x; As[ak+ 9][am]=a2.y; As[ak+10][am]=a2.z; As[ak+11][am]=a2.w;
      As[ak+12][am]=a3.x; As[ak+13][am]=a3.y; As[ak+14][am]=a3.z; As[ak+15][am]=a3.w;
    }
    {
      int bk = tid>>3, bn = (tid&7)*8;
      const float* bsrc = W + (size_t)(k0+bk)*256 + n0 + bn;
      *(float4*)&Bs[bk][bn]   = *(const float4*)bsrc;
      *(float4*)&Bs[bk][bn+4] = *(const float4*)(bsrc+4);
    }
    __syncthreads();

    #pragma unroll
    for (int k=0;k<32;k++){
      float4 a0 = *(float4*)&As[k][ty*8];
      float4 a1 = *(float4*)&As[k][ty*8+4];
      float4 bv = *(float4*)&Bs[k][tx*4];
      float aa[8] = {a0.x,a0.y,a0.z,a0.w,a1.x,a1.y,a1.z,a1.w};
      float bb[4] = {bv.x,bv.y,bv.z,bv.w};
      #pragma unroll
      for (int i2=0;i2<8;i2++)
        #pragma unroll
        for (int j2=0;j2<4;j2++) acc[i2][j2] += aa[i2]*bb[j2];
    }
    __syncthreads();
  }
  int col = n0 + tx*4;
  float4 bv = *(const float4*)(bias + col);
  #pragma unroll
  for (int i2=0;i2<8;i2++){
    int row = m0 + ty*8 + i2;
    *(float4*)&out[(size_t)row*256 + col] =
      make_float4(acc[i2][0]+bv.x, acc[i2][1]+bv.y, acc[i2][2]+bv.z, acc[i2][3]+bv.w);
  }
}

// ---------------- launch ----------------
extern "C" void kernel_launch(void* const* d_in, const int* in_sizes, int n_in,
                              void* d_out, int out_size){
  const float* x     = (const float*)d_in[0];
  const float* w_qk  = (const float*)d_in[1];
  const float* w_v   = (const float*)d_in[2];
  const float* w_out = (const float*)d_in[3];
  const float* b_out = (const float*)d_in[4];
  const float* rot   = (const float*)d_in[5];
  float* out = (float*)d_out;

  frontend_kernel<<<(BATCH*640*256+255)/256, 256>>>(x);
  gemm_qkv_kernel<<<dim3(4,80), 256>>>(w_qk, w_v);
  bucket_kernel<<<(BHDIM*NHASH*T+255)/256, 256>>>(rot);
  sort_kernel<<<BHDIM*NHASH, 320>>>();
  cudaFuncSetAttribute(attn_kernel, cudaFuncAttributeMaxDynamicSharedMemorySize, SMEM_ATTN);
  attn_kernel<<<BHDIM*NCHUNK, 256, SMEM_ATTN>>>();
  combine_kernel<<<(BHDIM*T*8+255)/256, 256>>>();
  gemm_out_kernel<<<dim3(4,80), 256>>>(w_out, b_out, out);
}

// round 7
// speedup vs baseline: 1.2037x; 1.0465x over previous
#include <cuda_runtime.h>
#include <math.h>

#define BATCH   16
#define T       640
#define EMBD    256
#define HEADS   8
#define DHDIM   32
#define BHDIM   128      // BATCH*HEADS
#define NHASH   8
#define NCHUNK  80
#define NROWS   10240    // BATCH*T

// ---------------- scratch (device globals; no allocation allowed) ----------------
__device__ float g_tokens[NROWS*EMBD];
__device__ float g_qk[BHDIM*T*DHDIM];
__device__ float g_v [BHDIM*T*DHDIM];
__device__ int   g_bucket[BHDIM*NHASH*T];
__device__ int   g_sorted[BHDIM*NHASH*T];
__device__ float g_ohash[(size_t)BHDIM*NHASH*T*DHDIM];
__device__ float g_logit[BHDIM*NHASH*T];
__device__ float g_omerged[NROWS*EMBD];
// pre-transposed + pre-split weights: [n][k] layout, hi/lo planes
__device__ float g_wqkT_hi[EMBD*EMBD], g_wqkT_lo[EMBD*EMBD];
__device__ float g_wvT_hi [EMBD*EMBD], g_wvT_lo [EMBD*EMBD];
__device__ float g_woT_hi [EMBD*EMBD], g_woT_lo [EMBD*EMBD];

// ---------------- tf32 mma.sync helpers ----------------
__device__ __forceinline__ void mma_tf32(float* d, const unsigned* a, const unsigned* b){
  asm volatile(
    "mma.sync.aligned.m16n8k8.row.col.f32.tf32.tf32.f32 "
    "{%0,%1,%2,%3}, {%4,%5,%6,%7}, {%8,%9}, {%0,%1,%2,%3};"
    : "+f"(d[0]), "+f"(d[1]), "+f"(d[2]), "+f"(d[3])
    : "r"(a[0]), "r"(a[1]), "r"(a[2]), "r"(a[3]), "r"(b[0]), "r"(b[1]));
}
// cheap split: hi = x with low 13 mantissa bits zeroed (exact tf32 value), lo = x - hi
__device__ __forceinline__ void tf32_split(float x, unsigned &hi, unsigned &lo){
  unsigned hb = __float_as_uint(x) & 0xFFFFE000u;
  hi = hb;
  lo = __float_as_uint(x - __uint_as_float(hb));
}
__device__ __forceinline__ unsigned fu(float x){ return __float_as_uint(x); }

// ---------------- stage 0: weight transpose + split ----------------
__global__ void wsplit_kernel(const float* __restrict__ wqk,
                              const float* __restrict__ wv,
                              const float* __restrict__ wo){
  __shared__ float tile[32][33];
  int z = blockIdx.z;
  const float* src = (z==0) ? wqk : (z==1) ? wv : wo;
  float* dh = (z==0) ? g_wqkT_hi : (z==1) ? g_wvT_hi : g_woT_hi;
  float* dl = (z==0) ? g_wqkT_lo : (z==1) ? g_wvT_lo : g_woT_lo;
  int n0 = blockIdx.x*32, k0 = blockIdx.y*32;
  #pragma unroll
  for (int r=0;r<4;r++){
    int k = threadIdx.y + r*8;
    tile[k][threadIdx.x] = src[(k0+k)*EMBD + n0 + threadIdx.x];
  }
  __syncthreads();
  #pragma unroll
  for (int r=0;r<4;r++){
    int n = threadIdx.y + r*8;
    float v = tile[threadIdx.x][n];
    float hv = __uint_as_float(__float_as_uint(v) & 0xFFFFE000u);
    int oi = (n0+n)*EMBD + k0 + threadIdx.x;
    dh[oi] = hv;
    dl[oi] = v - hv;
  }
}

// ---------------- stage 1: maxpool + Haar DWT -> tokens ----------------
__global__ void frontend_kernel(const float* __restrict__ x){
  int idx = blockIdx.x*blockDim.x + threadIdx.x;
  if (idx >= BATCH*640*256) return;
  int p = idx & 255;
  int n = (idx >> 8) % 640;
  int b = idx / (640*256);
  int i = p >> 4, j = p & 15;
  float val;
  if (n < 128){
    const float* xp = x + (size_t)(b*128+n)*1024;
    float m = -INFINITY;
    int r0 = 2*i-1, c0 = 2*j-1;
    #pragma unroll
    for (int dr=0;dr<3;dr++){
      int r = r0+dr; if (r<0 || r>31) continue;
      #pragma unroll
      for (int dc=0;dc<3;dc++){
        int cc = c0+dc; if (cc<0 || cc>31) continue;
        m = fmaxf(m, xp[r*32+cc]);
      }
    }
    val = m;
  } else {
    int g  = (n-128)>>7;
    int ch = (n-128)&127;
    const float* xp = x + (size_t)(b*128+ch)*1024;
    float a  = xp[(2*i)*32 + 2*j];
    float bb = xp[(2*i)*32 + 2*j+1];
    float c  = xp[(2*i+1)*32 + 2*j];
    float d  = xp[(2*i+1)*32 + 2*j+1];
    if      (g==0) val = (a+bb+c+d)*0.5f;
    else if (g==1) val = (a-bb+c-d)*0.5f;
    else if (g==2) val = (a+bb-c-d)*0.5f;
    else           val = (a-bb-c+d)*0.5f;
  }
  g_tokens[idx] = val;
}

// ---------------- stage 2: fused qk/v GEMM, 3xTF32 tensor cores ----------------
// block: 128 rows x 64 cols, 8 warps, each warp 16 rows x 64 cols for BOTH outputs
#define SMEM_QKV ((128*36 + 4*64*36)*4)

__global__ __launch_bounds__(256) void gemm_qkv_tc(){
  extern __shared__ float sm[];
  float* s_a   = sm;                 // [128][36]
  float* s_b1h = s_a   + 128*36;     // [64][36]
  float* s_b1l = s_b1h + 64*36;
  float* s_b2h = s_b1l + 64*36;
  float* s_b2l = s_b2h + 64*36;

  int tid = threadIdx.x;
  int m0 = blockIdx.y*128, n0 = blockIdx.x*64;
  int warp = tid>>5, lane = tid&31;
  int g = lane>>2, tig = lane&3;
  int rA = warp*16 + g, rB = rA + 8;

  float acc1[8][4], acc2[8][4];
  #pragma unroll
  for (int nt=0;nt<8;nt++)
    #pragma unroll
    for (int u=0;u<4;u++){ acc1[nt][u]=0.f; acc2[nt][u]=0.f; }

  for (int kc=0;kc<EMBD;kc+=32){
    __syncthreads();
    // load A tile 128x32
    {
      int row = tid>>1, half = (tid&1)*16;
      const float* asrc = g_tokens + (size_t)(m0+row)*EMBD + kc + half;
      #pragma unroll
      for (int u=0;u<16;u+=4)
        *(float4*)&s_a[row*36 + half + u] = *(const float4*)(asrc+u);
    }
    // load B planes 64x32 each (pre-transposed, pre-split)
    {
      int n = tid>>2, kq = (tid&3)*8;
      size_t bo = (size_t)(n0+n)*EMBD + kc + kq;
      *(float4*)&s_b1h[n*36+kq]   = *(const float4*)&g_wqkT_hi[bo];
      *(float4*)&s_b1h[n*36+kq+4] = *(const float4*)&g_wqkT_hi[bo+4];
      *(float4*)&s_b1l[n*36+kq]   = *(const float4*)&g_wqkT_lo[bo];
      *(float4*)&s_b1l[n*36+kq+4] = *(const float4*)&g_wqkT_lo[bo+4];
      *(float4*)&s_b2h[n*36+kq]   = *(const float4*)&g_wvT_hi[bo];
      *(float4*)&s_b2h[n*36+kq+4] = *(const float4*)&g_wvT_hi[bo+4];
      *(float4*)&s_b2l[n*36+kq]   = *(const float4*)&g_wvT_lo[bo];
      *(float4*)&s_b2l[n*36+kq+4] = *(const float4*)&g_wvT_lo[bo+4];
    }
    __syncthreads();

    #pragma unroll
    for (int kk=0;kk<32;kk+=8){
      unsigned ah[4], al[4];
      tf32_split(s_a[rA*36+kk+tig],   ah[0], al[0]);
      tf32_split(s_a[rB*36+kk+tig],   ah[1], al[1]);
      tf32_split(s_a[rA*36+kk+tig+4], ah[2], al[2]);
      tf32_split(s_a[rB*36+kk+tig+4], ah[3], al[3]);
      #pragma unroll
      for (int nt=0;nt<8;nt++){
        int nr = nt*8 + g;
        unsigned b1h[2] = { fu(s_b1h[nr*36+kk+tig]), fu(s_b1h[nr*36+kk+tig+4]) };
        unsigned b1l[2] = { fu(s_b1l[nr*36+kk+tig]), fu(s_b1l[nr*36+kk+tig+4]) };
        mma_tf32(acc1[nt], ah, b1h);
        mma_tf32(acc1[nt], al, b1h);
        mma_tf32(acc1[nt], ah, b1l);
        unsigned b2h[2] = { fu(s_b2h[nr*36+kk+tig]), fu(s_b2h[nr*36+kk+tig+4]) };
        unsigned b2l[2] = { fu(s_b2l[nr*36+kk+tig]), fu(s_b2l[nr*36+kk+tig+4]) };
        mma_tf32(acc2[nt], ah, b2h);
        mma_tf32(acc2[nt], al, b2h);
        mma_tf32(acc2[nt], ah, b2l);
      }
    }
  }
  // epilogue: head-split layout, float2 stores
  int rowA = m0 + rA, rowB = m0 + rB;
  int bA = rowA/640, tokA = rowA - bA*640;
  int bB = rowB/640, tokB = rowB - bB*640;
  #pragma unroll
  for (int nt=0;nt<8;nt++){
    int col = n0 + nt*8 + 2*tig;
    int head = col>>5, dh = col&31;
    size_t oA = ((size_t)(bA*8+head)*640 + tokA)*32 + dh;
    size_t oB = ((size_t)(bB*8+head)*640 + tokB)*32 + dh;
    *(float2*)&g_qk[oA] = make_float2(acc1[nt][0], acc1[nt][1]);
    *(float2*)&g_v [oA] = make_float2(acc2[nt][0], acc2[nt][1]);
    *(float2*)&g_qk[oB] = make_float2(acc1[nt][2], acc1[nt][3]);
    *(float2*)&g_v [oB] = make_float2(acc2[nt][2], acc2[nt][3]);
  }
}

// ---------------- stage 3a: LSH bucket ids ----------------
__global__ void bucket_kernel(const float* __restrict__ rot){
  __shared__ float s_rot[32*NHASH*5];
  for (int i=threadIdx.x;i<1280;i+=blockDim.x) s_rot[i]=rot[i];
  __syncthreads();
  int idx = blockIdx.x*blockDim.x + threadIdx.x;
  if (idx >= BHDIM*NHASH*T) return;
  int pos = idx % 640;
  int h   = (idx/640) & 7;
  int bh  = idx / (NHASH*T);
  const float* q = g_qk + ((size_t)bh*640 + pos)*32;
  float r[5] = {0.f,0.f,0.f,0.f,0.f};
  #pragma unroll 8
  for (int f=0;f<32;f++){
    float qf = q[f];
    const float* rp = s_rot + f*40 + h*5;
    #pragma unroll
    for (int i=0;i<5;i++) r[i] += qf*rp[i];
  }
  float best = r[0]; int bi = 0;
  #pragma unroll
  for (int i=1;i<5;i++) if (r[i] > best){ best=r[i]; bi=i; }
  #pragma unroll
  for (int i=0;i<5;i++){ float v = -r[i]; if (v > best){ best=v; bi=5+i; } }
  g_bucket[idx] = bi;
}

// ---------------- stage 3b: stable counting sort per (bh, hash) ----------------
__global__ __launch_bounds__(320) void sort_kernel(){
  __shared__ int cnt[10], off[10];
  int bhh = blockIdx.x;
  const int* bk = g_bucket + bhh*640;
  int w = threadIdx.x>>5, lane = threadIdx.x&31;
  int count = 0;
  for (int base=0;base<640;base+=32){
    int bb = bk[base+lane];
    unsigned mask = __ballot_sync(0xffffffffu, bb==w);
    count += __popc(mask);
  }
  if (lane==0) cnt[w] = count;
  __syncthreads();
  if (threadIdx.x==0){
    int run=0;
    for (int b=0;b<10;b++){ off[b]=run; run+=cnt[b]; }
  }
  __syncthreads();
  int base_off = off[w]; int run = 0;
  int* out = g_sorted + bhh*640;
  for (int base=0;base<640;base+=32){
    int bb = bk[base+lane];
    unsigned mask = __ballot_sync(0xffffffffu, bb==w);
    if (bb==w){
      int slot = base_off + run + __popc(mask & ((1u<<lane)-1u));
      out[slot] = base+lane;
    }
    run += __popc(mask);
  }
}

// ---------------- stage 4: chunked attention, 3xTF32 mma.sync (mask splits) ----------------
#define Q_PAD 36
#define K_PAD 36
#define V_PAD 40
#define P_PAD 132
#define SMEM_ATTN ((64*P_PAD + 128*V_PAD + 2*128)*4 + (64+128)*4)

__global__ __launch_bounds__(256) void attn_kernel(){
  extern __shared__ char smem_raw[];
  float* s_p    = (float*)smem_raw;          // [64][132]
  float* s_q    = s_p;                       // [64][36]  alias
  float* s_k    = s_p + 64*Q_PAD;            // [128][36] alias
  float* s_v    = s_p + 64*P_PAD;            // [128][40]
  float* s_redm = s_v + 128*V_PAD;           // [2][64]
  float* s_reds = s_redm + 128;              // [2][64]
  int*   s_qt   = (int*)(s_reds + 128);      // [64]
  int*   s_kt   = s_qt + 64;                 // [128]

  int tid = threadIdx.x;
  int blk = blockIdx.x;
  int bh = blk / NCHUNK, c = blk % NCHUNK;
  int h  = c / 10;
  int pc = (c + NCHUNK - 1) % NCHUNK;
  int ph = pc / 10;
  const int* sortedbh = g_sorted + bh*NHASH*T;

  if (tid < 64)
    s_qt[tid] = sortedbh[h*640 + (c%10)*64 + tid];
  else if (tid < 192){
    int j = tid - 64;
    s_kt[j] = (j < 64) ? sortedbh[h*640 + (c%10)*64 + j]
                       : sortedbh[ph*640 + (pc%10)*64 + (j-64)];
  }
  __syncthreads();

  // Q row-major [64][36]
  {
    int i = tid >> 2, f0 = (tid & 3) * 8;
    const float* src = g_qk + ((size_t)bh*640 + s_qt[i])*32 + f0;
    *(float4*)&s_q[i*Q_PAD + f0]     = *(const float4*)src;
    *(float4*)&s_q[i*Q_PAD + f0 + 4] = *(const float4*)(src+4);
  }
  // K row-major [128][36], normalized
  {
    int j = tid >> 1, fh = (tid & 1) * 16;
    const float* src = g_qk + ((size_t)bh*640 + s_kt[j])*32 + fh;
    float buf[16]; float ss = 0.f;
    #pragma unroll
    for (int u=0;u<16;u+=4){
      float4 a = *(const float4*)(src+u);
      buf[u]=a.x; buf[u+1]=a.y; buf[u+2]=a.z; buf[u+3]=a.w;
      ss += a.x*a.x + a.y*a.y + a.z*a.z + a.w*a.w;
    }
    ss += __shfl_xor_sync(0xffffffffu, ss, 1);
    float inv = 1.f / fmaxf(sqrtf(ss), 1e-6f);
    #pragma unroll
    for (int u=0;u<16;u+=4)
      *(float4*)&s_k[j*K_PAD + fh + u] =
        make_float4(buf[u]*inv, buf[u+1]*inv, buf[u+2]*inv, buf[u+3]*inv);
  }
  // V row-major [128][40]
  {
    int j = tid >> 1, fh = (tid & 1) * 16;
    const float* src = g_v + ((size_t)bh*640 + s_kt[j])*32 + fh;
    #pragma unroll
    for (int u=0;u<16;u+=4)
      *(float4*)&s_v[j*V_PAD + fh + u] = *(const float4*)(src+u);
  }
  __syncthreads();

  int warp = tid >> 5, lane = tid & 31;
  int wm = warp & 3, wn = warp >> 2;
  int g = lane >> 2, tig = lane & 3;
  int m0 = wm * 16;
  int rA = m0 + g, rB = m0 + g + 8;

  // ---- dots: S(16x64 per warp) = Q x K^T, 3xTF32 ----
  float acc[8][4];
  #pragma unroll
  for (int nt=0;nt<8;nt++)
    #pragma unroll
    for (int u=0;u<4;u++) acc[nt][u] = 0.f;

  #pragma unroll
  for (int k0=0;k0<32;k0+=8){
    unsigned ah[4], al[4];
    tf32_split(s_q[rA*Q_PAD + k0 + tig],     ah[0], al[0]);
    tf32_split(s_q[rB*Q_PAD + k0 + tig],     ah[1], al[1]);
    tf32_split(s_q[rA*Q_PAD + k0 + tig + 4], ah[2], al[2]);
    tf32_split(s_q[rB*Q_PAD + k0 + tig + 4], ah[3], al[3]);
    #pragma unroll
    for (int nt=0;nt<8;nt++){
      int n0 = wn*64 + nt*8;
      unsigned bhh[2], bll[2];
      tf32_split(s_k[(n0+g)*K_PAD + k0 + tig],     bhh[0], bll[0]);
      tf32_split(s_k[(n0+g)*K_PAD + k0 + tig + 4], bhh[1], bll[1]);
      mma_tf32(acc[nt], ah, bhh);
      mma_tf32(acc[nt], al, bhh);
      mma_tf32(acc[nt], ah, bll);
    }
  }

  // scale + self-mask
  int qtA = s_qt[rA], qtB = s_qt[rB];
  #pragma unroll
  for (int nt=0;nt<8;nt++){
    int n0 = wn*64 + nt*8;
    int kt0 = s_kt[n0 + 2*tig], kt1 = s_kt[n0 + 2*tig + 1];
    acc[nt][0] = (kt0==qtA) ? -50000.f : acc[nt][0]*0.17677669529663687f;
    acc[nt][1] = (kt1==qtA) ? -50000.f : acc[nt][1]*0.17677669529663687f;
    acc[nt][2] = (kt0==qtB) ? -50000.f : acc[nt][2]*0.17677669529663687f;
    acc[nt][3] = (kt1==qtB) ? -50000.f : acc[nt][3]*0.17677669529663687f;
  }

  float mA=-INFINITY, mB=-INFINITY;
  #pragma unroll
  for (int nt=0;nt<8;nt++){
    mA = fmaxf(mA, fmaxf(acc[nt][0], acc[nt][1]));
    mB = fmaxf(mB, fmaxf(acc[nt][2], acc[nt][3]));
  }
  #pragma unroll
  for (int o=1;o<=2;o<<=1){
    mA = fmaxf(mA, __shfl_xor_sync(0xffffffffu, mA, o, 4));
    mB = fmaxf(mB, __shfl_xor_sync(0xffffffffu, mB, o, 4));
  }
  float sA=0.f, sB=0.f;
  #pragma unroll
  for (int nt=0;nt<8;nt++){
    acc[nt][0] = __expf(acc[nt][0]-mA);
    acc[nt][1] = __expf(acc[nt][1]-mA);
    acc[nt][2] = __expf(acc[nt][2]-mB);
    acc[nt][3] = __expf(acc[nt][3]-mB);
    sA += acc[nt][0] + acc[nt][1];
    sB += acc[nt][2] + acc[nt][3];
  }
  #pragma unroll
  for (int o=1;o<=2;o<<=1){
    sA += __shfl_xor_sync(0xffffffffu, sA, o, 4);
    sB += __shfl_xor_sync(0xffffffffu, sB, o, 4);
  }
  if (tig == 0){
    s_redm[wn*64 + rA] = mA;  s_reds[wn*64 + rA] = sA;
    s_redm[wn*64 + rB] = mB;  s_reds[wn*64 + rB] = sB;
  }
  __syncthreads();

  float lseA, lseB;
  {
    float m0A = s_redm[rA], m1A = s_redm[64+rA];
    float mm = fmaxf(m0A, m1A);
    float ss = s_reds[rA]*__expf(m0A-mm) + s_reds[64+rA]*__expf(m1A-mm);
    lseA = mm + __logf(ss);
    float m0B = s_redm[rB], m1B = s_redm[64+rB];
    mm = fmaxf(m0B, m1B);
    ss = s_reds[rB]*__expf(m0B-mm) + s_reds[64+rB]*__expf(m1B-mm);
    lseB = mm + __logf(ss);
  }
  if (wn == 0 && tig == 0){
    g_logit[(bh*NHASH+h)*T + qtA] = lseA;
    g_logit[(bh*NHASH+h)*T + qtB] = lseB;
  }

  float scA = __expf(mA - lseA);
  float scB = __expf(mB - lseB);
  #pragma unroll
  for (int nt=0;nt<8;nt++){
    int n0 = wn*64 + nt*8;
    *(float2*)&s_p[rA*P_PAD + n0 + 2*tig] =
      make_float2(acc[nt][0]*scA, acc[nt][1]*scA);
    *(float2*)&s_p[rB*P_PAD + n0 + 2*tig] =
      make_float2(acc[nt][2]*scB, acc[nt][3]*scB);
  }
  __syncthreads();

  // ---- PV: O(16x16 per warp) = P(16x128) x V(128x32), 3xTF32 ----
  float o0[4] = {0.f,0.f,0.f,0.f};
  float o1[4] = {0.f,0.f,0.f,0.f};
  int d0 = wn*16;
  #pragma unroll 2
  for (int k0=0;k0<128;k0+=8){
    unsigned ah[4], al[4];
    tf32_split(s_p[rA*P_PAD + k0 + tig],     ah[0], al[0]);
    tf32_split(s_p[rB*P_PAD + k0 + tig],     ah[1], al[1]);
    tf32_split(s_p[rA*P_PAD + k0 + tig + 4], ah[2], al[2]);
    tf32_split(s_p[rB*P_PAD + k0 + tig + 4], ah[3], al[3]);
    unsigned b0h[2], b0l[2], b1h[2], b1l[2];
    tf32_split(s_v[(k0+tig)*V_PAD   + d0 + g],     b0h[0], b0l[0]);
    tf32_split(s_v[(k0+tig+4)*V_PAD + d0 + g],     b0h[1], b0l[1]);
    tf32_split(s_v[(k0+tig)*V_PAD   + d0 + 8 + g], b1h[0], b1l[0]);
    tf32_split(s_v[(k0+tig+4)*V_PAD + d0 + 8 + g], b1h[1], b1l[1]);
    mma_tf32(o0, ah, b0h);
    mma_tf32(o0, al, b0h);
    mma_tf32(o0, ah, b0l);
    mma_tf32(o1, ah, b1h);
    mma_tf32(o1, al, b1h);
    mma_tf32(o1, ah, b1l);
  }
  {
    size_t base = (size_t)(bh*NHASH+h)*T;
    float* dA = g_ohash + (base + qtA)*32;
    float* dB = g_ohash + (base + qtB)*32;
    *(float2*)(dA + d0 + 2*tig)     = make_float2(o0[0], o0[1]);
    *(float2*)(dB + d0 + 2*tig)     = make_float2(o0[2], o0[3]);
    *(float2*)(dA + d0 + 8 + 2*tig) = make_float2(o1[0], o1[1]);
    *(float2*)(dB + d0 + 8 + 2*tig) = make_float2(o1[2], o1[3]);
  }
}

// ---------------- stage 5: combine hashes, merge heads (float4) ----------------
__global__ void combine_kernel(){
  int idx = blockIdx.x*blockDim.x + threadIdx.x;
  if (idx >= BHDIM*T*8) return;
  int dq  = idx & 7;
  int pos = (idx >> 3) % 640;
  int bh  = idx / (640*8);
  float l[NHASH];
  #pragma unroll
  for (int h=0;h<NHASH;h++) l[h] = g_logit[(bh*NHASH+h)*T + pos];
  float m = l[0];
  #pragma unroll
  for (int h=1;h<NHASH;h++) m = fmaxf(m, l[h]);
  float s = 0.f;
  float e[NHASH];
  #pragma unroll
  for (int h=0;h<NHASH;h++){ e[h] = __expf(l[h]-m); s += e[h]; }
  float inv = 1.f/s;
  float4 acc = make_float4(0.f,0.f,0.f,0.f);
  #pragma unroll
  for (int h=0;h<NHASH;h++){
    float w = e[h]*inv;
    float4 v = *(const float4*)(g_ohash + ((size_t)(bh*NHASH+h)*T + pos)*32 + dq*4);
    acc.x += w*v.x; acc.y += w*v.y; acc.z += w*v.z; acc.w += w*v.w;
  }
  int b = bh>>3, head = bh&7;
  *(float4*)(g_omerged + ((size_t)b*640 + pos)*256 + head*32 + dq*4) = acc;
}

// ---------------- stage 6: output GEMM + bias, 3xTF32 tensor cores ----------------
__global__ __launch_bounds__(256) void gemm_out_tc(const float* __restrict__ bias,
                                                   float* __restrict__ out){
  __shared__ float s_a[128*36];
  __shared__ float s_bh[64*36];
  __shared__ float s_bl[64*36];

  int tid = threadIdx.x;
  int m0 = blockIdx.y*128, n0 = blockIdx.x*64;
  int warp = tid>>5, lane = tid&31;
  int g = lane>>2, tig = lane&3;
  int rA = warp*16 + g, rB = rA + 8;

  float acc[8][4];
  #pragma unroll
  for (int nt=0;nt<8;nt++)
    #pragma unroll
    for (int u=0;u<4;u++) acc[nt][u]=0.f;

  for (int kc=0;kc<EMBD;kc+=32){
    __syncthreads();
    {
      int row = tid>>1, half = (tid&1)*16;
      const float* asrc = g_omerged + (size_t)(m0+row)*EMBD + kc + half;
      #pragma unroll
      for (int u=0;u<16;u+=4)
        *(float4*)&s_a[row*36 + half + u] = *(const float4*)(asrc+u);
    }
    {
      int n = tid>>2, kq = (tid&3)*8;
      size_t bo = (size_t)(n0+n)*EMBD + kc + kq;
      *(float4*)&s_bh[n*36+kq]   = *(const float4*)&g_woT_hi[bo];
      *(float4*)&s_bh[n*36+kq+4] = *(const float4*)&g_woT_hi[bo+4];
      *(float4*)&s_bl[n*36+kq]   = *(const float4*)&g_woT_lo[bo];
      *(float4*)&s_bl[n*36+kq+4] = *(const float4*)&g_woT_lo[bo+4];
    }
    __syncthreads();

    #pragma unroll
    for (int kk=0;kk<32;kk+=8){
      unsigned ah[4], al[4];
      tf32_split(s_a[rA*36+kk+tig],   ah[0], al[0]);
      tf32_split(s_a[rB*36+kk+tig],   ah[1], al[1]);
      tf32_split(s_a[rA*36+kk+tig+4], ah[2], al[2]);
      tf32_split(s_a[rB*36+kk+tig+4], ah[3], al[3]);
      #pragma unroll
      for (int nt=0;nt<8;nt++){
        int nr = nt*8 + g;
        unsigned bhv[2] = { fu(s_bh[nr*36+kk+tig]), fu(s_bh[nr*36+kk+tig+4]) };
        unsigned blv[2] = { fu(s_bl[nr*36+kk+tig]), fu(s_bl[nr*36+kk+tig+4]) };
        mma_tf32(acc[nt], ah, bhv);
        mma_tf32(acc[nt], al, bhv);
        mma_tf32(acc[nt], ah, blv);
      }
    }
  }
  int rowA = m0 + rA, rowB = m0 + rB;
  #pragma unroll
  for (int nt=0;nt<8;nt++){
    int col = n0 + nt*8 + 2*tig;
    float b0 = __ldg(bias+col), b1 = __ldg(bias+col+1);
    *(float2*)&out[(size_t)rowA*EMBD + col] = make_float2(acc[nt][0]+b0, acc[nt][1]+b1);
    *(float2*)&out[(size_t)rowB*EMBD + col] = make_float2(acc[nt][2]+b0, acc[nt][3]+b1);
  }
}

// ---------------- launch ----------------
extern "C" void kernel_launch(void* const* d_in, const int* in_sizes, int n_in,
                              void* d_out, int out_size){
  const float* x     = (const float*)d_in[0];
  const float* w_qk  = (const float*)d_in[1];
  const float* w_v   = (const float*)d_in[2];
  const float* w_out = (const float*)d_in[3];
  const float* b_out = (const float*)d_in[4];
  const float* rot   = (const float*)d_in[5];
  float* out = (float*)d_out;

  wsplit_kernel<<<dim3(8,8,3), dim3(32,8)>>>(w_qk, w_v, w_out);
  frontend_kernel<<<(BATCH*640*256+255)/256, 256>>>(x);
  cudaFuncSetAttribute(gemm_qkv_tc, cudaFuncAttributeMaxDynamicSharedMemorySize, SMEM_QKV);
  gemm_qkv_tc<<<dim3(4,80), 256, SMEM_QKV>>>();
  bucket_kernel<<<(BHDIM*NHASH*T+255)/256, 256>>>(rot);
  sort_kernel<<<BHDIM*NHASH, 320>>>();
  cudaFuncSetAttribute(attn_kernel, cudaFuncAttributeMaxDynamicSharedMemorySize, SMEM_ATTN);
  attn_kernel<<<BHDIM*NCHUNK, 256, SMEM_ATTN>>>();
  combine_kernel<<<(BHDIM*T*8+255)/256, 256>>>();
  gemm_out_tc<<<dim3(4,80), 256>>>(b_out, out);
}

// round 8
// speedup vs baseline: 1.4255x; 1.1842x over previous
#include <cuda_runtime.h>
#include <math.h>

#define BATCH   16
#define T       640
#define EMBD    256
#define HEADS   8
#define DHDIM   32
#define BHDIM   128      // BATCH*HEADS
#define NHASH   8
#define NCHUNK  80
#define NROWS   10240    // BATCH*T

// ---------------- scratch (device globals; no allocation allowed) ----------------
__device__ float g_tokens[NROWS*EMBD];
__device__ float g_qk[BHDIM*T*DHDIM];
__device__ float g_v [BHDIM*T*DHDIM];
__device__ int   g_bucket[BHDIM*NHASH*T];
__device__ int   g_sorted[BHDIM*NHASH*T];
__device__ float g_ohash[(size_t)BHDIM*NHASH*T*DHDIM];
__device__ float g_logit[BHDIM*NHASH*T];
__device__ float g_omerged[NROWS*EMBD];
// pre-transposed + pre-split weights: [n][k] layout, hi/lo planes
__device__ float g_wqkT_hi[EMBD*EMBD], g_wqkT_lo[EMBD*EMBD];
__device__ float g_wvT_hi [EMBD*EMBD], g_wvT_lo [EMBD*EMBD];
__device__ float g_woT_hi [EMBD*EMBD], g_woT_lo [EMBD*EMBD];

// ---------------- tf32 mma.sync helpers ----------------
__device__ __forceinline__ void mma_tf32(float* d, const unsigned* a, const unsigned* b){
  asm volatile(
    "mma.sync.aligned.m16n8k8.row.col.f32.tf32.tf32.f32 "
    "{%0,%1,%2,%3}, {%4,%5,%6,%7}, {%8,%9}, {%0,%1,%2,%3};"
    : "+f"(d[0]), "+f"(d[1]), "+f"(d[2]), "+f"(d[3])
    : "r"(a[0]), "r"(a[1]), "r"(a[2]), "r"(a[3]), "r"(b[0]), "r"(b[1]));
}
// cheap split: hi = x with low 13 mantissa bits zeroed (exact tf32 value), lo = x - hi
__device__ __forceinline__ void tf32_split(float x, unsigned &hi, unsigned &lo){
  unsigned hb = __float_as_uint(x) & 0xFFFFE000u;
  hi = hb;
  lo = __float_as_uint(x - __uint_as_float(hb));
}
__device__ __forceinline__ unsigned fu(float x){ return __float_as_uint(x); }

// ---------------- stage 0: weight transpose + split ----------------
__global__ void wsplit_kernel(const float* __restrict__ wqk,
                              const float* __restrict__ wv,
                              const float* __restrict__ wo){
  __shared__ float tile[32][33];
  int z = blockIdx.z;
  const float* src = (z==0) ? wqk : (z==1) ? wv : wo;
  float* dh = (z==0) ? g_wqkT_hi : (z==1) ? g_wvT_hi : g_woT_hi;
  float* dl = (z==0) ? g_wqkT_lo : (z==1) ? g_wvT_lo : g_woT_lo;
  int n0 = blockIdx.x*32, k0 = blockIdx.y*32;
  #pragma unroll
  for (int r=0;r<4;r++){
    int k = threadIdx.y + r*8;
    tile[k][threadIdx.x] = src[(k0+k)*EMBD + n0 + threadIdx.x];
  }
  __syncthreads();
  #pragma unroll
  for (int r=0;r<4;r++){
    int n = threadIdx.y + r*8;
    float v = tile[threadIdx.x][n];
    float hv = __uint_as_float(__float_as_uint(v) & 0xFFFFE000u);
    int oi = (n0+n)*EMBD + k0 + threadIdx.x;
    dh[oi] = hv;
    dl[oi] = v - hv;
  }
}

// ---------------- stage 1: maxpool + Haar DWT -> tokens ----------------
__global__ void frontend_kernel(const float* __restrict__ x){
  int idx = blockIdx.x*blockDim.x + threadIdx.x;
  if (idx >= BATCH*640*256) return;
  int p = idx & 255;
  int n = (idx >> 8) % 640;
  int b = idx / (640*256);
  int i = p >> 4, j = p & 15;
  float val;
  if (n < 128){
    const float* xp = x + (size_t)(b*128+n)*1024;
    float m = -INFINITY;
    int r0 = 2*i-1, c0 = 2*j-1;
    #pragma unroll
    for (int dr=0;dr<3;dr++){
      int r = r0+dr; if (r<0 || r>31) continue;
      #pragma unroll
      for (int dc=0;dc<3;dc++){
        int cc = c0+dc; if (cc<0 || cc>31) continue;
        m = fmaxf(m, xp[r*32+cc]);
      }
    }
    val = m;
  } else {
    int g  = (n-128)>>7;
    int ch = (n-128)&127;
    const float* xp = x + (size_t)(b*128+ch)*1024;
    float a  = xp[(2*i)*32 + 2*j];
    float bb = xp[(2*i)*32 + 2*j+1];
    float c  = xp[(2*i+1)*32 + 2*j];
    float d  = xp[(2*i+1)*32 + 2*j+1];
    if      (g==0) val = (a+bb+c+d)*0.5f;
    else if (g==1) val = (a-bb+c-d)*0.5f;
    else if (g==2) val = (a+bb-c-d)*0.5f;
    else           val = (a-bb-c+d)*0.5f;
  }
  g_tokens[idx] = val;
}

// ---------------- stage 2: fused qk/v GEMM, 3xTF32 tensor cores ----------------
#define SMEM_QKV ((128*36 + 4*64*36)*4)

__global__ __launch_bounds__(256) void gemm_qkv_tc(){
  extern __shared__ float sm[];
  float* s_a   = sm;                 // [128][36]
  float* s_b1h = s_a   + 128*36;     // [64][36]
  float* s_b1l = s_b1h + 64*36;
  float* s_b2h = s_b1l + 64*36;
  float* s_b2l = s_b2h + 64*36;

  int tid = threadIdx.x;
  int m0 = blockIdx.y*128, n0 = blockIdx.x*64;
  int warp = tid>>5, lane = tid&31;
  int g = lane>>2, tig = lane&3;
  int rA = warp*16 + g, rB = rA + 8;

  float acc1[8][4], acc2[8][4];
  #pragma unroll
  for (int nt=0;nt<8;nt++)
    #pragma unroll
    for (int u=0;u<4;u++){ acc1[nt][u]=0.f; acc2[nt][u]=0.f; }

  for (int kc=0;kc<EMBD;kc+=32){
    __syncthreads();
    {
      int row = tid>>1, half = (tid&1)*16;
      const float* asrc = g_tokens + (size_t)(m0+row)*EMBD + kc + half;
      #pragma unroll
      for (int u=0;u<16;u+=4)
        *(float4*)&s_a[row*36 + half + u] = *(const float4*)(asrc+u);
    }
    {
      int n = tid>>2, kq = (tid&3)*8;
      size_t bo = (size_t)(n0+n)*EMBD + kc + kq;
      *(float4*)&s_b1h[n*36+kq]   = *(const float4*)&g_wqkT_hi[bo];
      *(float4*)&s_b1h[n*36+kq+4] = *(const float4*)&g_wqkT_hi[bo+4];
      *(float4*)&s_b1l[n*36+kq]   = *(const float4*)&g_wqkT_lo[bo];
      *(float4*)&s_b1l[n*36+kq+4] = *(const float4*)&g_wqkT_lo[bo+4];
      *(float4*)&s_b2h[n*36+kq]   = *(const float4*)&g_wvT_hi[bo];
      *(float4*)&s_b2h[n*36+kq+4] = *(const float4*)&g_wvT_hi[bo+4];
      *(float4*)&s_b2l[n*36+kq]   = *(const float4*)&g_wvT_lo[bo];
      *(float4*)&s_b2l[n*36+kq+4] = *(const float4*)&g_wvT_lo[bo+4];
    }
    __syncthreads();

    #pragma unroll
    for (int kk=0;kk<32;kk+=8){
      unsigned ah[4], al[4];
      tf32_split(s_a[rA*36+kk+tig],   ah[0], al[0]);
      tf32_split(s_a[rB*36+kk+tig],   ah[1], al[1]);
      tf32_split(s_a[rA*36+kk+tig+4], ah[2], al[2]);
      tf32_split(s_a[rB*36+kk+tig+4], ah[3], al[3]);
      #pragma unroll
      for (int nt=0;nt<8;nt++){
        int nr = nt*8 + g;
        unsigned b1h[2] = { fu(s_b1h[nr*36+kk+tig]), fu(s_b1h[nr*36+kk+tig+4]) };
        unsigned b1l[2] = { fu(s_b1l[nr*36+kk+tig]), fu(s_b1l[nr*36+kk+tig+4]) };
        mma_tf32(acc1[nt], ah, b1h);
        mma_tf32(acc1[nt], al, b1h);
        mma_tf32(acc1[nt], ah, b1l);
        unsigned b2h[2] = { fu(s_b2h[nr*36+kk+tig]), fu(s_b2h[nr*36+kk+tig+4]) };
        unsigned b2l[2] = { fu(s_b2l[nr*36+kk+tig]), fu(s_b2l[nr*36+kk+tig+4]) };
        mma_tf32(acc2[nt], ah, b2h);
        mma_tf32(acc2[nt], al, b2h);
        mma_tf32(acc2[nt], ah, b2l);
      }
    }
  }
  int rowA = m0 + rA, rowB = m0 + rB;
  int bA = rowA/640, tokA = rowA - bA*640;
  int bB = rowB/640, tokB = rowB - bB*640;
  #pragma unroll
  for (int nt=0;nt<8;nt++){
    int col = n0 + nt*8 + 2*tig;
    int head = col>>5, dh = col&31;
    size_t oA = ((size_t)(bA*8+head)*640 + tokA)*32 + dh;
    size_t oB = ((size_t)(bB*8+head)*640 + tokB)*32 + dh;
    *(float2*)&g_qk[oA] = make_float2(acc1[nt][0], acc1[nt][1]);
    *(float2*)&g_v [oA] = make_float2(acc2[nt][0], acc2[nt][1]);
    *(float2*)&g_qk[oB] = make_float2(acc1[nt][2], acc1[nt][3]);
    *(float2*)&g_v [oB] = make_float2(acc2[nt][2], acc2[nt][3]);
  }
}

// ---------------- stage 3a: LSH bucket ids — tiled, coalesced ----------------
// block = (bh, 32-pos tile); 256 threads = 32 pos x 8 hashes
__global__ __launch_bounds__(256) void bucket_kernel(const float* __restrict__ rot){
  __shared__ float s_rot[1280];        // [f=32][h=8][i=5]
  __shared__ float s_q[32][33];        // padded
  __shared__ int   s_b[8][32];
  int bh = blockIdx.x, pos0 = blockIdx.y*32;

  for (int i=threadIdx.x;i<1280;i+=256) s_rot[i]=rot[i];
  {
    int r = threadIdx.x>>3, fq = (threadIdx.x&7)*4;
    const float* src = g_qk + ((size_t)bh*640 + pos0 + r)*32 + fq;
    float4 v = *(const float4*)src;
    s_q[r][fq]=v.x; s_q[r][fq+1]=v.y; s_q[r][fq+2]=v.z; s_q[r][fq+3]=v.w;
  }
  __syncthreads();

  {
    int h = threadIdx.x & 7, pl = threadIdx.x >> 3;
    float r5[5] = {0.f,0.f,0.f,0.f,0.f};
    #pragma unroll 8
    for (int f=0;f<32;f++){
      float qf = s_q[pl][f];
      const float* rp = s_rot + f*40 + h*5;
      #pragma unroll
      for (int i=0;i<5;i++) r5[i] += qf*rp[i];
    }
    float best = r5[0]; int bi = 0;
    #pragma unroll
    for (int i=1;i<5;i++) if (r5[i] > best){ best=r5[i]; bi=i; }
    #pragma unroll
    for (int i=0;i<5;i++){ float v = -r5[i]; if (v > best){ best=v; bi=5+i; } }
    s_b[h][pl] = bi;
  }
  __syncthreads();

  // coalesced write: thread tid -> h = tid>>5, pos = tid&31
  {
    int h = threadIdx.x >> 5, pl = threadIdx.x & 31;
    g_bucket[(size_t)bh*NHASH*T + h*640 + pos0 + pl] = s_b[h][pl];
  }
}

// ---------------- stage 3b: stable counting sort per (bh, hash) ----------------
__global__ __launch_bounds__(320) void sort_kernel(){
  __shared__ int cnt[10], off[10];
  int bhh = blockIdx.x;
  const int* bk = g_bucket + bhh*640;
  int w = threadIdx.x>>5, lane = threadIdx.x&31;
  int count = 0;
  for (int base=0;base<640;base+=32){
    int bb = bk[base+lane];
    unsigned mask = __ballot_sync(0xffffffffu, bb==w);
    count += __popc(mask);
  }
  if (lane==0) cnt[w] = count;
  __syncthreads();
  if (threadIdx.x==0){
    int run=0;
    for (int b=0;b<10;b++){ off[b]=run; run+=cnt[b]; }
  }
  __syncthreads();
  int base_off = off[w]; int run = 0;
  int* out = g_sorted + bhh*640;
  for (int base=0;base<640;base+=32){
    int bb = bk[base+lane];
    unsigned mask = __ballot_sync(0xffffffffu, bb==w);
    if (bb==w){
      int slot = base_off + run + __popc(mask & ((1u<<lane)-1u));
      out[slot] = base+lane;
    }
    run += __popc(mask);
  }
}

// ---------------- stage 4: chunked attention, 3xTF32 mma.sync (mask splits) ----------------
#define Q_PAD 36
#define K_PAD 36
#define V_PAD 40
#define P_PAD 132
#define SMEM_ATTN ((64*P_PAD + 128*V_PAD + 2*128)*4 + (64+128)*4)

__global__ __launch_bounds__(256) void attn_kernel(){
  extern __shared__ char smem_raw[];
  float* s_p    = (float*)smem_raw;          // [64][132]
  float* s_q    = s_p;                       // [64][36]  alias
  float* s_k    = s_p + 64*Q_PAD;            // [128][36] alias
  float* s_v    = s_p + 64*P_PAD;            // [128][40]
  float* s_redm = s_v + 128*V_PAD;           // [2][64]
  float* s_reds = s_redm + 128;              // [2][64]
  int*   s_qt   = (int*)(s_reds + 128);      // [64]
  int*   s_kt   = s_qt + 64;                 // [128]

  int tid = threadIdx.x;
  int blk = blockIdx.x;
  int bh = blk / NCHUNK, c = blk % NCHUNK;
  int h  = c / 10;
  int pc = (c + NCHUNK - 1) % NCHUNK;
  int ph = pc / 10;
  const int* sortedbh = g_sorted + bh*NHASH*T;

  if (tid < 64)
    s_qt[tid] = sortedbh[h*640 + (c%10)*64 + tid];
  else if (tid < 192){
    int j = tid - 64;
    s_kt[j] = (j < 64) ? sortedbh[h*640 + (c%10)*64 + j]
                       : sortedbh[ph*640 + (pc%10)*64 + (j-64)];
  }
  __syncthreads();

  {
    int i = tid >> 2, f0 = (tid & 3) * 8;
    const float* src = g_qk + ((size_t)bh*640 + s_qt[i])*32 + f0;
    *(float4*)&s_q[i*Q_PAD + f0]     = *(const float4*)src;
    *(float4*)&s_q[i*Q_PAD + f0 + 4] = *(const float4*)(src+4);
  }
  {
    int j = tid >> 1, fh = (tid & 1) * 16;
    const float* src = g_qk + ((size_t)bh*640 + s_kt[j])*32 + fh;
    float buf[16]; float ss = 0.f;
    #pragma unroll
    for (int u=0;u<16;u+=4){
      float4 a = *(const float4*)(src+u);
      buf[u]=a.x; buf[u+1]=a.y; buf[u+2]=a.z; buf[u+3]=a.w;
      ss += a.x*a.x + a.y*a.y + a.z*a.z + a.w*a.w;
    }
    ss += __shfl_xor_sync(0xffffffffu, ss, 1);
    float inv = 1.f / fmaxf(sqrtf(ss), 1e-6f);
    #pragma unroll
    for (int u=0;u<16;u+=4)
      *(float4*)&s_k[j*K_PAD + fh + u] =
        make_float4(buf[u]*inv, buf[u+1]*inv, buf[u+2]*inv, buf[u+3]*inv);
  }
  {
    int j = tid >> 1, fh = (tid & 1) * 16;
    const float* src = g_v + ((size_t)bh*640 + s_kt[j])*32 + fh;
    #pragma unroll
    for (int u=0;u<16;u+=4)
      *(float4*)&s_v[j*V_PAD + fh + u] = *(const float4*)(src+u);
  }
  __syncthreads();

  int warp = tid >> 5, lane = tid & 31;
  int wm = warp & 3, wn = warp >> 2;
  int g = lane >> 2, tig = lane & 3;
  int m0 = wm * 16;
  int rA = m0 + g, rB = m0 + g + 8;

  float acc[8][4];
  #pragma unroll
  for (int nt=0;nt<8;nt++)
    #pragma unroll
    for (int u=0;u<4;u++) acc[nt][u] = 0.f;

  #pragma unroll
  for (int k0=0;k0<32;k0+=8){
    unsigned ah[4], al[4];
    tf32_split(s_q[rA*Q_PAD + k0 + tig],     ah[0], al[0]);
    tf32_split(s_q[rB*Q_PAD + k0 + tig],     ah[1], al[1]);
    tf32_split(s_q[rA*Q_PAD + k0 + tig + 4], ah[2], al[2]);
    tf32_split(s_q[rB*Q_PAD + k0 + tig + 4], ah[3], al[3]);
    #pragma unroll
    for (int nt=0;nt<8;nt++){
      int n0 = wn*64 + nt*8;
      unsigned bhh[2], bll[2];
      tf32_split(s_k[(n0+g)*K_PAD + k0 + tig],     bhh[0], bll[0]);
      tf32_split(s_k[(n0+g)*K_PAD + k0 + tig + 4], bhh[1], bll[1]);
      mma_tf32(acc[nt], ah, bhh);
      mma_tf32(acc[nt], al, bhh);
      mma_tf32(acc[nt], ah, bll);
    }
  }

  int qtA = s_qt[rA], qtB = s_qt[rB];
  #pragma unroll
  for (int nt=0;nt<8;nt++){
    int n0 = wn*64 + nt*8;
    int kt0 = s_kt[n0 + 2*tig], kt1 = s_kt[n0 + 2*tig + 1];
    acc[nt][0] = (kt0==qtA) ? -50000.f : acc[nt][0]*0.17677669529663687f;
    acc[nt][1] = (kt1==qtA) ? -50000.f : acc[nt][1]*0.17677669529663687f;
    acc[nt][2] = (kt0==qtB) ? -50000.f : acc[nt][2]*0.17677669529663687f;
    acc[nt][3] = (kt1==qtB) ? -50000.f : acc[nt][3]*0.17677669529663687f;
  }

  float mA=-INFINITY, mB=-INFINITY;
  #pragma unroll
  for (int nt=0;nt<8;nt++){
    mA = fmaxf(mA, fmaxf(acc[nt][0], acc[nt][1]));
    mB = fmaxf(mB, fmaxf(acc[nt][2], acc[nt][3]));
  }
  #pragma unroll
  for (int o=1;o<=2;o<<=1){
    mA = fmaxf(mA, __shfl_xor_sync(0xffffffffu, mA, o, 4));
    mB = fmaxf(mB, __shfl_xor_sync(0xffffffffu, mB, o, 4));
  }
  float sA=0.f, sB=0.f;
  #pragma unroll
  for (int nt=0;nt<8;nt++){
    acc[nt][0] = __expf(acc[nt][0]-mA);
    acc[nt][1] = __expf(acc[nt][1]-mA);
    acc[nt][2] = __expf(acc[nt][2]-mB);
    acc[nt][3] = __expf(acc[nt][3]-mB);
    sA += acc[nt][0] + acc[nt][1];
    sB += acc[nt][2] + acc[nt][3];
  }
  #pragma unroll
  for (int o=1;o<=2;o<<=1){
    sA += __shfl_xor_sync(0xffffffffu, sA, o, 4);
    sB += __shfl_xor_sync(0xffffffffu, sB, o, 4);
  }
  if (tig == 0){
    s_redm[wn*64 + rA] = mA;  s_reds[wn*64 + rA] = sA;
    s_redm[wn*64 + rB] = mB;  s_reds[wn*64 + rB] = sB;
  }
  __syncthreads();

  float lseA, lseB;
  {
    float m0A = s_redm[rA], m1A = s_redm[64+rA];
    float mm = fmaxf(m0A, m1A);
    float ss = s_reds[rA]*__expf(m0A-mm) + s_reds[64+rA]*__expf(m1A-mm);
    lseA = mm + __logf(ss);
    float m0B = s_redm[rB], m1B = s_redm[64+rB];
    mm = fmaxf(m0B, m1B);
    ss = s_reds[rB]*__expf(m0B-mm) + s_reds[64+rB]*__expf(m1B-mm);
    lseB = mm + __logf(ss);
  }
  if (wn == 0 && tig == 0){
    g_logit[(bh*NHASH+h)*T + qtA] = lseA;
    g_logit[(bh*NHASH+h)*T + qtB] = lseB;
  }

  float scA = __expf(mA - lseA);
  float scB = __expf(mB - lseB);
  #pragma unroll
  for (int nt=0;nt<8;nt++){
    int n0 = wn*64 + nt*8;
    *(float2*)&s_p[rA*P_PAD + n0 + 2*tig] =
      make_float2(acc[nt][0]*scA, acc[nt][1]*scA);
    *(float2*)&s_p[rB*P_PAD + n0 + 2*tig] =
      make_float2(acc[nt][2]*scB, acc[nt][3]*scB);
  }
  __syncthreads();

  float o0[4] = {0.f,0.f,0.f,0.f};
  float o1[4] = {0.f,0.f,0.f,0.f};
  int d0 = wn*16;
  #pragma unroll 2
  for (int k0=0;k0<128;k0+=8){
    unsigned ah[4], al[4];
    tf32_split(s_p[rA*P_PAD + k0 + tig],     ah[0], al[0]);
    tf32_split(s_p[rB*P_PAD + k0 + tig],     ah[1], al[1]);
    tf32_split(s_p[rA*P_PAD + k0 + tig + 4], ah[2], al[2]);
    tf32_split(s_p[rB*P_PAD + k0 + tig + 4], ah[3], al[3]);
    unsigned b0h[2], b0l[2], b1h[2], b1l[2];
    tf32_split(s_v[(k0+tig)*V_PAD   + d0 + g],     b0h[0], b0l[0]);
    tf32_split(s_v[(k0+tig+4)*V_PAD + d0 + g],     b0h[1], b0l[1]);
    tf32_split(s_v[(k0+tig)*V_PAD   + d0 + 8 + g], b1h[0], b1l[0]);
    tf32_split(s_v[(k0+tig+4)*V_PAD + d0 + 8 + g], b1h[1], b1l[1]);
    mma_tf32(o0, ah, b0h);
    mma_tf32(o0, al, b0h);
    mma_tf32(o0, ah, b0l);
    mma_tf32(o1, ah, b1h);
    mma_tf32(o1, al, b1h);
    mma_tf32(o1, ah, b1l);
  }
  {
    size_t base = (size_t)(bh*NHASH+h)*T;
    float* dA = g_ohash + (base + qtA)*32;
    float* dB = g_ohash + (base + qtB)*32;
    *(float2*)(dA + d0 + 2*tig)     = make_float2(o0[0], o0[1]);
    *(float2*)(dB + d0 + 2*tig)     = make_float2(o0[2], o0[3]);
    *(float2*)(dA + d0 + 8 + 2*tig) = make_float2(o1[0], o1[1]);
    *(float2*)(dB + d0 + 8 + 2*tig) = make_float2(o1[2], o1[3]);
  }
}

// ---------------- stage 5: combine hashes, merge heads (float4) ----------------
__global__ void combine_kernel(){
  int idx = blockIdx.x*blockDim.x + threadIdx.x;
  if (idx >= BHDIM*T*8) return;
  int dq  = idx & 7;
  int pos = (idx >> 3) % 640;
  int bh  = idx / (640*8);
  float l[NHASH];
  #pragma unroll
  for (int h=0;h<NHASH;h++) l[h] = g_logit[(bh*NHASH+h)*T + pos];
  float m = l[0];
  #pragma unroll
  for (int h=1;h<NHASH;h++) m = fmaxf(m, l[h]);
  float s = 0.f;
  float e[NHASH];
  #pragma unroll
  for (int h=0;h<NHASH;h++){ e[h] = __expf(l[h]-m); s += e[h]; }
  float inv = 1.f/s;
  float4 acc = make_float4(0.f,0.f,0.f,0.f);
  #pragma unroll
  for (int h=0;h<NHASH;h++){
    float w = e[h]*inv;
    float4 v = *(const float4*)(g_ohash + ((size_t)(bh*NHASH+h)*T + pos)*32 + dq*4);
    acc.x += w*v.x; acc.y += w*v.y; acc.z += w*v.z; acc.w += w*v.w;
  }
  int b = bh>>3, head = bh&7;
  *(float4*)(g_omerged + ((size_t)b*640 + pos)*256 + head*32 + dq*4) = acc;
}

// ---------------- stage 6: output GEMM + bias, 3xTF32 tensor cores ----------------
__global__ __launch_bounds__(256) void gemm_out_tc(const float* __restrict__ bias,
                                                   float* __restrict__ out){
  __shared__ float s_a[128*36];
  __shared__ float s_bh[64*36];
  __shared__ float s_bl[64*36];

  int tid = threadIdx.x;
  int m0 = blockIdx.y*128, n0 = blockIdx.x*64;
  int warp = tid>>5, lane = tid&31;
  int g = lane>>2, tig = lane&3;
  int rA = warp*16 + g, rB = rA + 8;

  float acc[8][4];
  #pragma unroll
  for (int nt=0;nt<8;nt++)
    #pragma unroll
    for (int u=0;u<4;u++) acc[nt][u]=0.f;

  for (int kc=0;kc<EMBD;kc+=32){
    __syncthreads();
    {
      int row = tid>>1, half = (tid&1)*16;
      const float* asrc = g_omerged + (size_t)(m0+row)*EMBD + kc + half;
      #pragma unroll
      for (int u=0;u<16;u+=4)
        *(float4*)&s_a[row*36 + half + u] = *(const float4*)(asrc+u);
    }
    {
      int n = tid>>2, kq = (tid&3)*8;
      size_t bo = (size_t)(n0+n)*EMBD + kc + kq;
      *(float4*)&s_bh[n*36+kq]   = *(const float4*)&g_woT_hi[bo];
      *(float4*)&s_bh[n*36+kq+4] = *(const float4*)&g_woT_hi[bo+4];
      *(float4*)&s_bl[n*36+kq]   = *(const float4*)&g_woT_lo[bo];
      *(float4*)&s_bl[n*36+kq+4] = *(const float4*)&g_woT_lo[bo+4];
    }
    __syncthreads();

    #pragma unroll
    for (int kk=0;kk<32;kk+=8){
      unsigned ah[4], al[4];
      tf32_split(s_a[rA*36+kk+tig],   ah[0], al[0]);
      tf32_split(s_a[rB*36+kk+tig],   ah[1], al[1]);
      tf32_split(s_a[rA*36+kk+tig+4], ah[2], al[2]);
      tf32_split(s_a[rB*36+kk+tig+4], ah[3], al[3]);
      #pragma unroll
      for (int nt=0;nt<8;nt++){
        int nr = nt*8 + g;
        unsigned bhv[2] = { fu(s_bh[nr*36+kk+tig]), fu(s_bh[nr*36+kk+tig+4]) };
        unsigned blv[2] = { fu(s_bl[nr*36+kk+tig]), fu(s_bl[nr*36+kk+tig+4]) };
        mma_tf32(acc[nt], ah, bhv);
        mma_tf32(acc[nt], al, bhv);
        mma_tf32(acc[nt], ah, blv);
      }
    }
  }
  int rowA = m0 + rA, rowB = m0 + rB;
  #pragma unroll
  for (int nt=0;nt<8;nt++){
    int col = n0 + nt*8 + 2*tig;
    float b0 = __ldg(bias+col), b1 = __ldg(bias+col+1);
    *(float2*)&out[(size_t)rowA*EMBD + col] = make_float2(acc[nt][0]+b0, acc[nt][1]+b1);
    *(float2*)&out[(size_t)rowB*EMBD + col] = make_float2(acc[nt][2]+b0, acc[nt][3]+b1);
  }
}

// ---------------- launch ----------------
extern "C" void kernel_launch(void* const* d_in, const int* in_sizes, int n_in,
                              void* d_out, int out_size){
  const float* x     = (const float*)d_in[0];
  const float* w_qk  = (const float*)d_in[1];
  const float* w_v   = (const float*)d_in[2];
  const float* w_out = (const float*)d_in[3];
  const float* b_out = (const float*)d_in[4];
  const float* rot   = (const float*)d_in[5];
  float* out = (float*)d_out;

  wsplit_kernel<<<dim3(8,8,3), dim3(32,8)>>>(w_qk, w_v, w_out);
  frontend_kernel<<<(BATCH*640*256+255)/256, 256>>>(x);
  cudaFuncSetAttribute(gemm_qkv_tc, cudaFuncAttributeMaxDynamicSharedMemorySize, SMEM_QKV);
  gemm_qkv_tc<<<dim3(4,80), 256, SMEM_QKV>>>();
  bucket_kernel<<<dim3(BHDIM, T/32), 256>>>(rot);
  sort_kernel<<<BHDIM*NHASH, 320>>>();
  cudaFuncSetAttribute(attn_kernel, cudaFuncAttributeMaxDynamicSharedMemorySize, SMEM_ATTN);
  attn_kernel<<<BHDIM*NCHUNK, 256, SMEM_ATTN>>>();
  combine_kernel<<<(BHDIM*T*8+255)/256, 256>>>();
  gemm_out_tc<<<dim3(4,80), 256>>>(b_out, out);
}

// round 9
// speedup vs baseline: 1.4681x; 1.0299x over previous
#include <cuda_runtime.h>
#include <math.h>

#define BATCH   16
#define T       640
#define EMBD    256
#define HEADS   8
#define DHDIM   32
#define BHDIM   128      // BATCH*HEADS
#define NHASH   8
#define NCHUNK  80
#define NROWS   10240    // BATCH*T

// ---------------- scratch (device globals; no allocation allowed) ----------------
__device__ float g_tokens[NROWS*EMBD];
__device__ float g_qk[BHDIM*T*DHDIM];
__device__ float g_v [BHDIM*T*DHDIM];
__device__ int   g_bucket[BHDIM*NHASH*T];
__device__ int   g_sorted[BHDIM*NHASH*T];
__device__ float g_ohash[(size_t)BHDIM*NHASH*T*DHDIM];
__device__ float g_logit[BHDIM*NHASH*T];
__device__ float g_omerged[NROWS*EMBD];
// pre-transposed + pre-split weights: [n][k] layout, hi/lo planes
__device__ float g_wqkT_hi[EMBD*EMBD], g_wqkT_lo[EMBD*EMBD];
__device__ float g_wvT_hi [EMBD*EMBD], g_wvT_lo [EMBD*EMBD];
__device__ float g_woT_hi [EMBD*EMBD], g_woT_lo [EMBD*EMBD];

// ---------------- tf32 mma.sync helpers ----------------
__device__ __forceinline__ void mma_tf32(float* d, const unsigned* a, const unsigned* b){
  asm volatile(
    "mma.sync.aligned.m16n8k8.row.col.f32.tf32.tf32.f32 "
    "{%0,%1,%2,%3}, {%4,%5,%6,%7}, {%8,%9}, {%0,%1,%2,%3};"
    : "+f"(d[0]), "+f"(d[1]), "+f"(d[2]), "+f"(d[3])
    : "r"(a[0]), "r"(a[1]), "r"(a[2]), "r"(a[3]), "r"(b[0]), "r"(b[1]));
}
// cheap split: hi = x with low 13 mantissa bits zeroed (exact tf32 value), lo = x - hi
__device__ __forceinline__ void tf32_split(float x, unsigned &hi, unsigned &lo){
  unsigned hb = __float_as_uint(x) & 0xFFFFE000u;
  hi = hb;
  lo = __float_as_uint(x - __uint_as_float(hb));
}
__device__ __forceinline__ unsigned fu(float x){ return __float_as_uint(x); }

// ---------------- stage 0: weight transpose + split ----------------
__global__ void wsplit_kernel(const float* __restrict__ wqk,
                              const float* __restrict__ wv,
                              const float* __restrict__ wo){
  __shared__ float tile[32][33];
  int z = blockIdx.z;
  const float* src = (z==0) ? wqk : (z==1) ? wv : wo;
  float* dh = (z==0) ? g_wqkT_hi : (z==1) ? g_wvT_hi : g_woT_hi;
  float* dl = (z==0) ? g_wqkT_lo : (z==1) ? g_wvT_lo : g_woT_lo;
  int n0 = blockIdx.x*32, k0 = blockIdx.y*32;
  #pragma unroll
  for (int r=0;r<4;r++){
    int k = threadIdx.y + r*8;
    tile[k][threadIdx.x] = src[(k0+k)*EMBD + n0 + threadIdx.x];
  }
  __syncthreads();
  #pragma unroll
  for (int r=0;r<4;r++){
    int n = threadIdx.y + r*8;
    float v = tile[threadIdx.x][n];
    float hv = __uint_as_float(__float_as_uint(v) & 0xFFFFE000u);
    int oi = (n0+n)*EMBD + k0 + threadIdx.x;
    dh[oi] = hv;
    dl[oi] = v - hv;
  }
}

// ---------------- stage 1: maxpool + Haar DWT -> tokens (smem tiled) ----------------
// one block per (b, ch) 32x32 plane; 256 threads
__global__ __launch_bounds__(256) void frontend_kernel(const float* __restrict__ x){
  __shared__ float s_x[32][33];
  int plane = blockIdx.x;            // b*128 + ch
  int b = plane >> 7, ch = plane & 127;
  const float* xp = x + (size_t)plane*1024;
  int t = threadIdx.x;

  // coalesced plane load: thread t -> float4 at t*4
  {
    float4 v = *(const float4*)(xp + t*4);
    int r = t >> 3, c4 = (t & 7)*4;
    s_x[r][c4]=v.x; s_x[r][c4+1]=v.y; s_x[r][c4+2]=v.z; s_x[r][c4+3]=v.w;
  }
  __syncthreads();

  int i = t >> 4, j = t & 15;
  // maxpool 3x3 s2 p1 (same fmaxf order as before -> bit-identical)
  float m = -INFINITY;
  int r0 = 2*i-1, c0 = 2*j-1;
  #pragma unroll
  for (int dr=0;dr<3;dr++){
    int r = r0+dr; if (r<0 || r>31) continue;
    #pragma unroll
    for (int dc=0;dc<3;dc++){
      int cc = c0+dc; if (cc<0 || cc>31) continue;
      m = fmaxf(m, s_x[r][cc]);
    }
  }
  // Haar DWT quad
  float a  = s_x[2*i][2*j];
  float bb = s_x[2*i][2*j+1];
  float c  = s_x[2*i+1][2*j];
  float d  = s_x[2*i+1][2*j+1];
  float ll = (a+bb+c+d)*0.5f;
  float lh = (a-bb+c-d)*0.5f;
  float hl = (a+bb-c-d)*0.5f;
  float hh = (a-bb-c+d)*0.5f;

  size_t rowbase = (size_t)b*640;
  g_tokens[(rowbase + ch      )*256 + t] = m;
  g_tokens[(rowbase + 128 + ch)*256 + t] = ll;
  g_tokens[(rowbase + 256 + ch)*256 + t] = lh;
  g_tokens[(rowbase + 384 + ch)*256 + t] = hl;
  g_tokens[(rowbase + 512 + ch)*256 + t] = hh;
}

// ---------------- stage 2: fused qk/v GEMM, 3xTF32 tensor cores ----------------
#define SMEM_QKV ((128*36 + 4*64*36)*4)

__global__ __launch_bounds__(256) void gemm_qkv_tc(){
  extern __shared__ float sm[];
  float* s_a   = sm;                 // [128][36]
  float* s_b1h = s_a   + 128*36;     // [64][36]
  float* s_b1l = s_b1h + 64*36;
  float* s_b2h = s_b1l + 64*36;
  float* s_b2l = s_b2h + 64*36;

  int tid = threadIdx.x;
  int m0 = blockIdx.y*128, n0 = blockIdx.x*64;
  int warp = tid>>5, lane = tid&31;
  int g = lane>>2, tig = lane&3;
  int rA = warp*16 + g, rB = rA + 8;

  float acc1[8][4], acc2[8][4];
  #pragma unroll
  for (int nt=0;nt<8;nt++)
    #pragma unroll
    for (int u=0;u<4;u++){ acc1[nt][u]=0.f; acc2[nt][u]=0.f; }

  for (int kc=0;kc<EMBD;kc+=32){
    __syncthreads();
    {
      int row = tid>>1, half = (tid&1)*16;
      const float* asrc = g_tokens + (size_t)(m0+row)*EMBD + kc + half;
      #pragma unroll
      for (int u=0;u<16;u+=4)
        *(float4*)&s_a[row*36 + half + u] = *(const float4*)(asrc+u);
    }
    {
      int n = tid>>2, kq = (tid&3)*8;
      size_t bo = (size_t)(n0+n)*EMBD + kc + kq;
      *(float4*)&s_b1h[n*36+kq]   = *(const float4*)&g_wqkT_hi[bo];
      *(float4*)&s_b1h[n*36+kq+4] = *(const float4*)&g_wqkT_hi[bo+4];
      *(float4*)&s_b1l[n*36+kq]   = *(const float4*)&g_wqkT_lo[bo];
      *(float4*)&s_b1l[n*36+kq+4] = *(const float4*)&g_wqkT_lo[bo+4];
      *(float4*)&s_b2h[n*36+kq]   = *(const float4*)&g_wvT_hi[bo];
      *(float4*)&s_b2h[n*36+kq+4] = *(const float4*)&g_wvT_hi[bo+4];
      *(float4*)&s_b2l[n*36+kq]   = *(const float4*)&g_wvT_lo[bo];
      *(float4*)&s_b2l[n*36+kq+4] = *(const float4*)&g_wvT_lo[bo+4];
    }
    __syncthreads();

    #pragma unroll
    for (int kk=0;kk<32;kk+=8){
      unsigned ah[4], al[4];
      tf32_split(s_a[rA*36+kk+tig],   ah[0], al[0]);
      tf32_split(s_a[rB*36+kk+tig],   ah[1], al[1]);
      tf32_split(s_a[rA*36+kk+tig+4], ah[2], al[2]);
      tf32_split(s_a[rB*36+kk+tig+4], ah[3], al[3]);
      #pragma unroll
      for (int nt=0;nt<8;nt++){
        int nr = nt*8 + g;
        unsigned b1h[2] = { fu(s_b1h[nr*36+kk+tig]), fu(s_b1h[nr*36+kk+tig+4]) };
        unsigned b1l[2] = { fu(s_b1l[nr*36+kk+tig]), fu(s_b1l[nr*36+kk+tig+4]) };
        mma_tf32(acc1[nt], ah, b1h);
        mma_tf32(acc1[nt], al, b1h);
        mma_tf32(acc1[nt], ah, b1l);
        unsigned b2h[2] = { fu(s_b2h[nr*36+kk+tig]), fu(s_b2h[nr*36+kk+tig+4]) };
        unsigned b2l[2] = { fu(s_b2l[nr*36+kk+tig]), fu(s_b2l[nr*36+kk+tig+4]) };
        mma_tf32(acc2[nt], ah, b2h);
        mma_tf32(acc2[nt], al, b2h);
        mma_tf32(acc2[nt], ah, b2l);
      }
    }
  }
  int rowA = m0 + rA, rowB = m0 + rB;
  int bA = rowA/640, tokA = rowA - bA*640;
  int bB = rowB/640, tokB = rowB - bB*640;
  #pragma unroll
  for (int nt=0;nt<8;nt++){
    int col = n0 + nt*8 + 2*tig;
    int head = col>>5, dh = col&31;
    size_t oA = ((size_t)(bA*8+head)*640 + tokA)*32 + dh;
    size_t oB = ((size_t)(bB*8+head)*640 + tokB)*32 + dh;
    *(float2*)&g_qk[oA] = make_float2(acc1[nt][0], acc1[nt][1]);
    *(float2*)&g_v [oA] = make_float2(acc2[nt][0], acc2[nt][1]);
    *(float2*)&g_qk[oB] = make_float2(acc1[nt][2], acc1[nt][3]);
    *(float2*)&g_v [oB] = make_float2(acc2[nt][2], acc2[nt][3]);
  }
}

// ---------------- stage 3a: LSH bucket ids — warp-per-hash, 4 pos/thread ----------------
// block = (bh, 128-pos tile); 256 threads = warp h (8 warps), lane l handles pos l+32k
__global__ __launch_bounds__(256) void bucket_kernel(const float* __restrict__ rot){
  __shared__ float s_rot[1280];        // [f=32][h=8][i=5]
  __shared__ float s_q[128][33];
  int bh = blockIdx.x, pos0 = blockIdx.y*128;
  int tid = threadIdx.x;

  for (int i=tid;i<1280;i+=256) s_rot[i]=rot[i];
  {
    int row = tid>>1, fh = (tid&1)*16;
    const float* src = g_qk + ((size_t)bh*640 + pos0 + row)*32 + fh;
    #pragma unroll
    for (int u=0;u<16;u+=4){
      float4 v = *(const float4*)(src+u);
      s_q[row][fh+u]=v.x; s_q[row][fh+u+1]=v.y; s_q[row][fh+u+2]=v.z; s_q[row][fh+u+3]=v.w;
    }
  }
  __syncthreads();

  int h = tid>>5, l = tid&31;
  float r5[4][5];
  #pragma unroll
  for (int k=0;k<4;k++)
    #pragma unroll
    for (int i=0;i<5;i++) r5[k][i]=0.f;

  #pragma unroll 4
  for (int f=0;f<32;f++){
    const float* rp = s_rot + f*40 + h*5;   // warp-uniform -> broadcast
    float w0=rp[0], w1=rp[1], w2=rp[2], w3=rp[3], w4=rp[4];
    #pragma unroll
    for (int k=0;k<4;k++){
      float qf = s_q[l + 32*k][f];
      r5[k][0] += qf*w0; r5[k][1] += qf*w1; r5[k][2] += qf*w2;
      r5[k][3] += qf*w3; r5[k][4] += qf*w4;
    }
  }
  #pragma unroll
  for (int k=0;k<4;k++){
    float best = r5[k][0]; int bi = 0;
    #pragma unroll
    for (int i=1;i<5;i++) if (r5[k][i] > best){ best=r5[k][i]; bi=i; }
    #pragma unroll
    for (int i=0;i<5;i++){ float v = -r5[k][i]; if (v > best){ best=v; bi=5+i; } }
    g_bucket[(size_t)bh*NHASH*T + h*640 + pos0 + l + 32*k] = bi;
  }
}

// ---------------- stage 3b: stable counting sort per (bh, hash) ----------------
__global__ __launch_bounds__(320) void sort_kernel(){
  __shared__ int cnt[10], off[10];
  int bhh = blockIdx.x;
  const int* bk = g_bucket + bhh*640;
  int w = threadIdx.x>>5, lane = threadIdx.x&31;
  int count = 0;
  for (int base=0;base<640;base+=32){
    int bb = bk[base+lane];
    unsigned mask = __ballot_sync(0xffffffffu, bb==w);
    count += __popc(mask);
  }
  if (lane==0) cnt[w] = count;
  __syncthreads();
  if (threadIdx.x==0){
    int run=0;
    for (int b=0;b<10;b++){ off[b]=run; run+=cnt[b]; }
  }
  __syncthreads();
  int base_off = off[w]; int run = 0;
  int* out = g_sorted + bhh*640;
  for (int base=0;base<640;base+=32){
    int bb = bk[base+lane];
    unsigned mask = __ballot_sync(0xffffffffu, bb==w);
    if (bb==w){
      int slot = base_off + run + __popc(mask & ((1u<<lane)-1u));
      out[slot] = base+lane;
    }
    run += __popc(mask);
  }
}

// ---------------- stage 4: chunked attention, 3xTF32 mma.sync (mask splits) ----------------
#define Q_PAD 36
#define K_PAD 36
#define V_PAD 40
#define P_PAD 132
#define SMEM_ATTN ((64*P_PAD + 128*V_PAD + 2*128)*4 + (64+128)*4)

__global__ __launch_bounds__(256) void attn_kernel(){
  extern __shared__ char smem_raw[];
  float* s_p    = (float*)smem_raw;          // [64][132]
  float* s_q    = s_p;                       // [64][36]  alias
  float* s_k    = s_p + 64*Q_PAD;            // [128][36] alias
  float* s_v    = s_p + 64*P_PAD;            // [128][40]
  float* s_redm = s_v + 128*V_PAD;           // [2][64]
  float* s_reds = s_redm + 128;              // [2][64]
  int*   s_qt   = (int*)(s_reds + 128);      // [64]
  int*   s_kt   = s_qt + 64;                 // [128]

  int tid = threadIdx.x;
  int blk = blockIdx.x;
  int bh = blk / NCHUNK, c = blk % NCHUNK;
  int h  = c / 10;
  int pc = (c + NCHUNK - 1) % NCHUNK;
  int ph = pc / 10;
  const int* sortedbh = g_sorted + bh*NHASH*T;

  if (tid < 64)
    s_qt[tid] = sortedbh[h*640 + (c%10)*64 + tid];
  else if (tid < 192){
    int j = tid - 64;
    s_kt[j] = (j < 64) ? sortedbh[h*640 + (c%10)*64 + j]
                       : sortedbh[ph*640 + (pc%10)*64 + (j-64)];
  }
  __syncthreads();

  {
    int i = tid >> 2, f0 = (tid & 3) * 8;
    const float* src = g_qk + ((size_t)bh*640 + s_qt[i])*32 + f0;
    *(float4*)&s_q[i*Q_PAD + f0]     = *(const float4*)src;
    *(float4*)&s_q[i*Q_PAD + f0 + 4] = *(const float4*)(src+4);
  }
  {
    int j = tid >> 1, fh = (tid & 1) * 16;
    const float* src = g_qk + ((size_t)bh*640 + s_kt[j])*32 + fh;
    float buf[16]; float ss = 0.f;
    #pragma unroll
    for (int u=0;u<16;u+=4){
      float4 a = *(const float4*)(src+u);
      buf[u]=a.x; buf[u+1]=a.y; buf[u+2]=a.z; buf[u+3]=a.w;
      ss += a.x*a.x + a.y*a.y + a.z*a.z + a.w*a.w;
    }
    ss += __shfl_xor_sync(0xffffffffu, ss, 1);
    float inv = 1.f / fmaxf(sqrtf(ss), 1e-6f);
    #pragma unroll
    for (int u=0;u<16;u+=4)
      *(float4*)&s_k[j*K_PAD + fh + u] =
        make_float4(buf[u]*inv, buf[u+1]*inv, buf[u+2]*inv, buf[u+3]*inv);
  }
  {
    int j = tid >> 1, fh = (tid & 1) * 16;
    const float* src = g_v + ((size_t)bh*640 + s_kt[j])*32 + fh;
    #pragma unroll
    for (int u=0;u<16;u+=4)
      *(float4*)&s_v[j*V_PAD + fh + u] = *(const float4*)(src+u);
  }
  __syncthreads();

  int warp = tid >> 5, lane = tid & 31;
  int wm = warp & 3, wn = warp >> 2;
  int g = lane >> 2, tig = lane & 3;
  int m0 = wm * 16;
  int rA = m0 + g, rB = m0 + g + 8;

  float acc[8][4];
  #pragma unroll
  for (int nt=0;nt<8;nt++)
    #pragma unroll
    for (int u=0;u<4;u++) acc[nt][u] = 0.f;

  #pragma unroll
  for (int k0=0;k0<32;k0+=8){
    unsigned ah[4], al[4];
    tf32_split(s_q[rA*Q_PAD + k0 + tig],     ah[0], al[0]);
    tf32_split(s_q[rB*Q_PAD + k0 + tig],     ah[1], al[1]);
    tf32_split(s_q[rA*Q_PAD + k0 + tig + 4], ah[2], al[2]);
    tf32_split(s_q[rB*Q_PAD + k0 + tig + 4], ah[3], al[3]);
    #pragma unroll
    for (int nt=0;nt<8;nt++){
      int n0 = wn*64 + nt*8;
      unsigned bhh[2], bll[2];
      tf32_split(s_k[(n0+g)*K_PAD + k0 + tig],     bhh[0], bll[0]);
      tf32_split(s_k[(n0+g)*K_PAD + k0 + tig + 4], bhh[1], bll[1]);
      mma_tf32(acc[nt], ah, bhh);
      mma_tf32(acc[nt], al, bhh);
      mma_tf32(acc[nt], ah, bll);
    }
  }

  int qtA = s_qt[rA], qtB = s_qt[rB];
  #pragma unroll
  for (int nt=0;nt<8;nt++){
    int n0 = wn*64 + nt*8;
    int kt0 = s_kt[n0 + 2*tig], kt1 = s_kt[n0 + 2*tig + 1];
    acc[nt][0] = (kt0==qtA) ? -50000.f : acc[nt][0]*0.17677669529663687f;
    acc[nt][1] = (kt1==qtA) ? -50000.f : acc[nt][1]*0.17677669529663687f;
    acc[nt][2] = (kt0==qtB) ? -50000.f : acc[nt][2]*0.17677669529663687f;
    acc[nt][3] = (kt1==qtB) ? -50000.f : acc[nt][3]*0.17677669529663687f;
  }

  float mA=-INFINITY, mB=-INFINITY;
  #pragma unroll
  for (int nt=0;nt<8;nt++){
    mA = fmaxf(mA, fmaxf(acc[nt][0], acc[nt][1]));
    mB = fmaxf(mB, fmaxf(acc[nt][2], acc[nt][3]));
  }
  #pragma unroll
  for (int o=1;o<=2;o<<=1){
    mA = fmaxf(mA, __shfl_xor_sync(0xffffffffu, mA, o, 4));
    mB = fmaxf(mB, __shfl_xor_sync(0xffffffffu, mB, o, 4));
  }
  float sA=0.f, sB=0.f;
  #pragma unroll
  for (int nt=0;nt<8;nt++){
    acc[nt][0] = __expf(acc[nt][0]-mA);
    acc[nt][1] = __expf(acc[nt][1]-mA);
    acc[nt][2] = __expf(acc[nt][2]-mB);
    acc[nt][3] = __expf(acc[nt][3]-mB);
    sA += acc[nt][0] + acc[nt][1];
    sB += acc[nt][2] + acc[nt][3];
  }
  #pragma unroll
  for (int o=1;o<=2;o<<=1){
    sA += __shfl_xor_sync(0xffffffffu, sA, o, 4);
    sB += __shfl_xor_sync(0xffffffffu, sB, o, 4);
  }
  if (tig == 0){
    s_redm[wn*64 + rA] = mA;  s_reds[wn*64 + rA] = sA;
    s_redm[wn*64 + rB] = mB;  s_reds[wn*64 + rB] = sB;
  }
  __syncthreads();

  float lseA, lseB;
  {
    float m0A = s_redm[rA], m1A = s_redm[64+rA];
    float mm = fmaxf(m0A, m1A);
    float ss = s_reds[rA]*__expf(m0A-mm) + s_reds[64+rA]*__expf(m1A-mm);
    lseA = mm + __logf(ss);
    float m0B = s_redm[rB], m1B = s_redm[64+rB];
    mm = fmaxf(m0B, m1B);
    ss = s_reds[rB]*__expf(m0B-mm) + s_reds[64+rB]*__expf(m1B-mm);
    lseB = mm + __logf(ss);
  }
  if (wn == 0 && tig == 0){
    g_logit[(bh*NHASH+h)*T + qtA] = lseA;
    g_logit[(bh*NHASH+h)*T + qtB] = lseB;
  }

  float scA = __expf(mA - lseA);
  float scB = __expf(mB - lseB);
  #pragma unroll
  for (int nt=0;nt<8;nt++){
    int n0 = wn*64 + nt*8;
    *(float2*)&s_p[rA*P_PAD + n0 + 2*tig] =
      make_float2(acc[nt][0]*scA, acc[nt][1]*scA);
    *(float2*)&s_p[rB*P_PAD + n0 + 2*tig] =
      make_float2(acc[nt][2]*scB, acc[nt][3]*scB);
  }
  __syncthreads();

  float o0[4] = {0.f,0.f,0.f,0.f};
  float o1[4] = {0.f,0.f,0.f,0.f};
  int d0 = wn*16;
  #pragma unroll 2
  for (int k0=0;k0<128;k0+=8){
    unsigned ah[4], al[4];
    tf32_split(s_p[rA*P_PAD + k0 + tig],     ah[0], al[0]);
    tf32_split(s_p[rB*P_PAD + k0 + tig],     ah[1], al[1]);
    tf32_split(s_p[rA*P_PAD + k0 + tig + 4], ah[2], al[2]);
    tf32_split(s_p[rB*P_PAD + k0 + tig + 4], ah[3], al[3]);
    unsigned b0h[2], b0l[2], b1h[2], b1l[2];
    tf32_split(s_v[(k0+tig)*V_PAD   + d0 + g],     b0h[0], b0l[0]);
    tf32_split(s_v[(k0+tig+4)*V_PAD + d0 + g],     b0h[1], b0l[1]);
    tf32_split(s_v[(k0+tig)*V_PAD   + d0 + 8 + g], b1h[0], b1l[0]);
    tf32_split(s_v[(k0+tig+4)*V_PAD + d0 + 8 + g], b1h[1], b1l[1]);
    mma_tf32(o0, ah, b0h);
    mma_tf32(o0, al, b0h);
    mma_tf32(o0, ah, b0l);
    mma_tf32(o1, ah, b1h);
    mma_tf32(o1, al, b1h);
    mma_tf32(o1, ah, b1l);
  }
  {
    size_t base = (size_t)(bh*NHASH+h)*T;
    float* dA = g_ohash + (base + qtA)*32;
    float* dB = g_ohash + (base + qtB)*32;
    *(float2*)(dA + d0 + 2*tig)     = make_float2(o0[0], o0[1]);
    *(float2*)(dB + d0 + 2*tig)     = make_float2(o0[2], o0[3]);
    *(float2*)(dA + d0 + 8 + 2*tig) = make_float2(o1[0], o1[1]);
    *(float2*)(dB + d0 + 8 + 2*tig) = make_float2(o1[2], o1[3]);
  }
}

// ---------------- stage 5: combine hashes, merge heads (float4) ----------------
__global__ void combine_kernel(){
  int idx = blockIdx.x*blockDim.x + threadIdx.x;
  if (idx >= BHDIM*T*8) return;
  int dq  = idx & 7;
  int pos = (idx >> 3) % 640;
  int bh  = idx / (640*8);
  float l[NHASH];
  #pragma unroll
  for (int h=0;h<NHASH;h++) l[h] = g_logit[(bh*NHASH+h)*T + pos];
  float m = l[0];
  #pragma unroll
  for (int h=1;h<NHASH;h++) m = fmaxf(m, l[h]);
  float s = 0.f;
  float e[NHASH];
  #pragma unroll
  for (int h=0;h<NHASH;h++){ e[h] = __expf(l[h]-m); s += e[h]; }
  float inv = 1.f/s;
  float4 acc = make_float4(0.f,0.f,0.f,0.f);
  #pragma unroll
  for (int h=0;h<NHASH;h++){
    float w = e[h]*inv;
    float4 v = *(const float4*)(g_ohash + ((size_t)(bh*NHASH+h)*T + pos)*32 + dq*4);
    acc.x += w*v.x; acc.y += w*v.y; acc.z += w*v.z; acc.w += w*v.w;
  }
  int b = bh>>3, head = bh&7;
  *(float4*)(g_omerged + ((size_t)b*640 + pos)*256 + head*32 + dq*4) = acc;
}

// ---------------- stage 6: output GEMM + bias, 3xTF32 tensor cores ----------------
__global__ __launch_bounds__(256) void gemm_out_tc(const float* __restrict__ bias,
                                                   float* __restrict__ out){
  __shared__ float s_a[128*36];
  __shared__ float s_bh[64*36];
  __shared__ float s_bl[64*36];

  int tid = threadIdx.x;
  int m0 = blockIdx.y*128, n0 = blockIdx.x*64;
  int warp = tid>>5, lane = tid&31;
  int g = lane>>2, tig = lane&3;
  int rA = warp*16 + g, rB = rA + 8;

  float acc[8][4];
  #pragma unroll
  for (int nt=0;nt<8;nt++)
    #pragma unroll
    for (int u=0;u<4;u++) acc[nt][u]=0.f;

  for (int kc=0;kc<EMBD;kc+=32){
    __syncthreads();
    {
      int row = tid>>1, half = (tid&1)*16;
      const float* asrc = g_omerged + (size_t)(m0+row)*EMBD + kc + half;
      #pragma unroll
      for (int u=0;u<16;u+=4)
        *(float4*)&s_a[row*36 + half + u] = *(const float4*)(asrc+u);
    }
    {
      int n = tid>>2, kq = (tid&3)*8;
      size_t bo = (size_t)(n0+n)*EMBD + kc + kq;
      *(float4*)&s_bh[n*36+kq]   = *(const float4*)&g_woT_hi[bo];
      *(float4*)&s_bh[n*36+kq+4] = *(const float4*)&g_woT_hi[bo+4];
      *(float4*)&s_bl[n*36+kq]   = *(const float4*)&g_woT_lo[bo];
      *(float4*)&s_bl[n*36+kq+4] = *(const float4*)&g_woT_lo[bo+4];
    }
    __syncthreads();

    #pragma unroll
    for (int kk=0;kk<32;kk+=8){
      unsigned ah[4], al[4];
      tf32_split(s_a[rA*36+kk+tig],   ah[0], al[0]);
      tf32_split(s_a[rB*36+kk+tig],   ah[1], al[1]);
      tf32_split(s_a[rA*36+kk+tig+4], ah[2], al[2]);
      tf32_split(s_a[rB*36+kk+tig+4], ah[3], al[3]);
      #pragma unroll
      for (int nt=0;nt<8;nt++){
        int nr = nt*8 + g;
        unsigned bhv[2] = { fu(s_bh[nr*36+kk+tig]), fu(s_bh[nr*36+kk+tig+4]) };
        unsigned blv[2] = { fu(s_bl[nr*36+kk+tig]), fu(s_bl[nr*36+kk+tig+4]) };
        mma_tf32(acc[nt], ah, bhv);
        mma_tf32(acc[nt], al, bhv);
        mma_tf32(acc[nt], ah, blv);
      }
    }
  }
  int rowA = m0 + rA, rowB = m0 + rB;
  #pragma unroll
  for (int nt=0;nt<8;nt++){
    int col = n0 + nt*8 + 2*tig;
    float b0 = __ldg(bias+col), b1 = __ldg(bias+col+1);
    *(float2*)&out[(size_t)rowA*EMBD + col] = make_float2(acc[nt][0]+b0, acc[nt][1]+b1);
    *(float2*)&out[(size_t)rowB*EMBD + col] = make_float2(acc[nt][2]+b0, acc[nt][3]+b1);
  }
}

// ---------------- launch ----------------
extern "C" void kernel_launch(void* const* d_in, const int* in_sizes, int n_in,
                              void* d_out, int out_size){
  const float* x     = (const float*)d_in[0];
  const float* w_qk  = (const float*)d_in[1];
  const float* w_v   = (const float*)d_in[2];
  const float* w_out = (const float*)d_in[3];
  const float* b_out = (const float*)d_in[4];
  const float* rot   = (const float*)d_in[5];
  float* out = (float*)d_out;

  wsplit_kernel<<<dim3(8,8,3), dim3(32,8)>>>(w_qk, w_v, w_out);
  frontend_kernel<<<BATCH*128, 256>>>(x);
  cudaFuncSetAttribute(gemm_qkv_tc, cudaFuncAttributeMaxDynamicSharedMemorySize, SMEM_QKV);
  gemm_qkv_tc<<<dim3(4,80), 256, SMEM_QKV>>>();
  bucket_kernel<<<dim3(BHDIM, T/128), 256>>>(rot);
  sort_kernel<<<BHDIM*NHASH, 320>>>();
  cudaFuncSetAttribute(attn_kernel, cudaFuncAttributeMaxDynamicSharedMemorySize, SMEM_ATTN);
  attn_kernel<<<BHDIM*NCHUNK, 256, SMEM_ATTN>>>();
  combine_kernel<<<(BHDIM*T*8+255)/256, 256>>>();
  gemm_out_tc<<<dim3(4,80), 256>>>(b_out, out);
}